// round 15
// baseline (speedup 1.0000x reference)
#include <cuda_runtime.h>
#include <cuda_fp16.h>
#include <math.h>
#include <stdint.h>

// ---------------- problem constants ----------------
#define NTOK   4096          // N*T = 2*2048
#define TSEQ   2048
#define DM     1024          // d_model
#define DIP    4384          // d_in_proj
#define DINNER 2048
#define CONVD  2304          // d_inner + 2*d_state
#define HS     32            // ssm heads
#define PD     64            // headdim
#define DS     128           // d_state
#define CH     256           // chunk
#define NC     8             // chunks per sequence

// ---------------- scratch layout (floats) ----------------
#define OFF_Q    0ull                 // 4096*1024   roped q (residual)
#define OFF_ZX   8388608ull           // 4096*4384   zxbcdt
#define OFF_XBC  26345472ull          // 4096*2304   conv+silu output
#define OFF_DT   35782656ull          // 4096*32     softplus dt
#define OFF_G    35913728ull          // 16*256*256  G^T per (b,c): [s][l]
#define OFF_ST   36962304ull          // 16*32*64*128 chunk states -> states_prev
#define OFF_ASUM 41156608ull          // 2*32*8      chunk A sums
#define OFF_EACS 41157120ull          // 16*32*256   exp(Acs)
#define OFF_Y    41288192ull          // 4096*2048   y
// fp16 arrays (offsets in floats; 1 float = 2 halves)
#define OFF_XHI  58065408ull
#define OFF_WIH  62259712ull
#define OFF_WZH  63308288ull
#define OFF_WOH  67797504ull
#define OFF_HH   69894656ull
#define OFF_YGH  74088960ull
#define OFF_BCH  82477568ull
#define OFF_TAB  83526144ull          // 2048*32 float2 rope table
#define SCRATCH_FLOATS 83657216ull

__device__ float g_scratch[SCRATCH_FLOATS];

typedef __half hf;

// =====================================================================
//  helpers
// =====================================================================
__device__ __forceinline__ uint32_t sm32(const void* p) {
    return (uint32_t)__cvta_generic_to_shared(p);
}
__device__ __forceinline__ void ldsm_x4(uint32_t& r0, uint32_t& r1, uint32_t& r2, uint32_t& r3,
                                        uint32_t a) {
    asm volatile("ldmatrix.sync.aligned.m8n8.x4.shared.b16 {%0,%1,%2,%3}, [%4];"
                 : "=r"(r0), "=r"(r1), "=r"(r2), "=r"(r3) : "r"(a));
}
__device__ __forceinline__ void ldsm_x4_t(uint32_t& r0, uint32_t& r1, uint32_t& r2, uint32_t& r3,
                                          uint32_t a) {
    asm volatile("ldmatrix.sync.aligned.m8n8.x4.trans.shared.b16 {%0,%1,%2,%3}, [%4];"
                 : "=r"(r0), "=r"(r1), "=r"(r2), "=r"(r3) : "r"(a));
}
__device__ __forceinline__ void mma16816h(float* c, const uint32_t* a, uint32_t b0, uint32_t b1) {
    asm volatile(
        "mma.sync.aligned.m16n8k16.row.col.f32.f16.f16.f32 "
        "{%0,%1,%2,%3}, {%4,%5,%6,%7}, {%8,%9}, {%0,%1,%2,%3};"
        : "+f"(c[0]), "+f"(c[1]), "+f"(c[2]), "+f"(c[3])
        : "r"(a[0]), "r"(a[1]), "r"(a[2]), "r"(a[3]), "r"(b0), "r"(b1));
}
__device__ __forceinline__ void cp16(uint32_t s, const void* g, int bytes) {
    asm volatile("cp.async.cg.shared.global [%0], [%1], 16, %2;"
                 :: "r"(s), "l"(g), "r"(bytes));
}
__device__ __forceinline__ uint32_t packh2(float a, float b) {
    __half2 h = __floats2half2_rn(a, b);
    return *(uint32_t*)&h;
}

// ---------------- rope sin/cos table ----------------
__global__ void __launch_bounds__(256)
rope_tab_kernel(float2* __restrict__ tab)
{
    int idx = blockIdx.x * blockDim.x + threadIdx.x;
    if (idx >= TSEQ * 32) return;
    int t = idx >> 5, j = idx & 31;
    float inv = exp2f(-(float)(2 * j) * (1.f / 64.f) * 13.287712379549449f);
    float c, s;
    sincosf((float)t * inv, &s, &c);
    tab[idx] = make_float2(c, s);
}

// fp32 -> fp16 (rn)
__global__ void __launch_bounds__(256)
cvt_hi(const float* __restrict__ in, hf* __restrict__ hi, int n4)
{
    int i = blockIdx.x * blockDim.x + threadIdx.x;
    if (i >= n4) return;
    float4 v = ((const float4*)in)[i];
    hf h[4];
    h[0] = __float2half_rn(v.x); h[1] = __float2half_rn(v.y);
    h[2] = __float2half_rn(v.z); h[3] = __float2half_rn(v.w);
    ((uint2*)hi)[i] = *(uint2*)h;
}

// =====================================================================
//  3-stage pipelined single-product fp16 GEMM, BK=64:
//  C = A(MxK)*B(NxK)^T (+addC); 128x128 tile, 256 thr = 8 warps (4x2)
// =====================================================================
#define BM 128
#define BN 128
#define BK 64
#define LDK 72                 // halves per smem row (144 B; first 64 real)
#define MAT  (BM * LDK)        // 9216 halves per matrix
#define STGX (2 * MAT)         // A, B
#define NSTAGE 3
#define GEMM_SMEM (NSTAGE * STGX * 2)   // 110592 bytes

__global__ void __launch_bounds__(256, 2)
gemm_hf1(const hf* __restrict__ Ah, const hf* __restrict__ Bh,
         float* __restrict__ C, const float* __restrict__ addC,
         int M, int N, int K, int lda, int ldb, int ldc,
         size_t bsA, size_t bsB, size_t bsC)
{
    extern __shared__ hf sm[];

    Ah += bsA * blockIdx.z;
    Bh += bsB * blockIdx.z;
    C  += bsC * blockIdx.z;

    int tid = threadIdx.x, lane = tid & 31, wid = tid >> 5;
    int warp_m = wid & 3, warp_n = wid >> 2;
    int m0 = blockIdx.y * BM, n0 = blockIdx.x * BN;

    float acc[2][8][4];
    #pragma unroll
    for (int mt = 0; mt < 2; mt++)
        #pragma unroll
        for (int nt = 0; nt < 8; nt++)
            #pragma unroll
            for (int e = 0; e < 4; e++) acc[mt][nt][e] = 0.f;

    const int KC = K >> 6;               // chunks of 64 (K % 64 == 0 for all uses)

    // loader: 1 row per thread pair-half; 4 x 16B chunks
    int r0   = tid >> 1;                 // 0..127
    int koff = (tid & 1) << 5;           // 0 or 32 halves
    bool bv0 = (n0 + r0) < N;
    int br0  = bv0 ? r0 : 0;

    auto load_stage = [&](int kc, int st) {
        hf* base = sm + st * STGX;
        uint32_t sa = sm32(base + r0 * LDK + koff);
        uint32_t sb = sa + 2 * MAT;      // halves -> bytes handled: MAT halves = 2*MAT bytes
        size_t ga = (size_t)(m0 + r0) * lda + kc + koff;
        size_t gb = (size_t)(n0 + br0) * ldb + kc + koff;
        #pragma unroll
        for (int q = 0; q < 4; q++) {
            cp16(sa + q * 16, Ah + ga + q * 8, 16);
            cp16(sb + q * 16, Bh + gb + q * 8, bv0 ? 16 : 0);
        }
    };

    int a_r = (lane & 15), a_k = ((lane >> 4) << 3);
    int bg = lane >> 3, bq = lane & 7;
    int b_row = ((bg >> 1) << 3) + bq;
    int b_ko  = (bg & 1) << 3;

    load_stage(0, 0);
    asm volatile("cp.async.commit_group;");
    load_stage(64, 1);                   // KC >= 2 for all launches
    asm volatile("cp.async.commit_group;");

    for (int c = 0; c < KC; c++) {
        if (c + 1 < KC) asm volatile("cp.async.wait_group 1;");
        else            asm volatile("cp.async.wait_group 0;");
        __syncthreads();

        if (c + 2 < KC) {
            load_stage((c + 2) << 6, (c + 2) % NSTAGE);
            asm volatile("cp.async.commit_group;");
        }

        hf* base = sm + (c % NSTAGE) * STGX;
        hf* sA = base;
        hf* sB = base + MAT;

        #pragma unroll
        for (int ks = 0; ks < 4; ks++) {
            int k0 = ks * 16;
            uint32_t ah[2][4];
            #pragma unroll
            for (int mt = 0; mt < 2; mt++) {
                int ar = (warp_m * 32 + mt * 16 + a_r) * LDK + k0 + a_k;
                ldsm_x4(ah[mt][0], ah[mt][1], ah[mt][2], ah[mt][3], sm32(&sA[ar]));
            }
            #pragma unroll
            for (int ntp = 0; ntp < 4; ntp++) {
                int br = (warp_n * 64 + ntp * 16 + b_row) * LDK + k0 + b_ko;
                uint32_t b0, b1, b2, b3;
                ldsm_x4(b0, b1, b2, b3, sm32(&sB[br]));
                #pragma unroll
                for (int mt = 0; mt < 2; mt++) {
                    mma16816h(acc[mt][ntp * 2 + 0], ah[mt], b0, b1);
                    mma16816h(acc[mt][ntp * 2 + 1], ah[mt], b2, b3);
                }
            }
        }
    }

    int tg = lane >> 2, tq = lane & 3;
    #pragma unroll
    for (int mt = 0; mt < 2; mt++) {
        int m = m0 + warp_m * 32 + mt * 16 + tg;
        #pragma unroll
        for (int nt = 0; nt < 8; nt++) {
            int n = n0 + warp_n * 64 + nt * 8 + tq * 2;
            if (n < N) {
                size_t o0 = (size_t)m * ldc + n;
                size_t o1 = (size_t)(m + 8) * ldc + n;
                float v0 = acc[mt][nt][0], v1 = acc[mt][nt][1];
                float v2 = acc[mt][nt][2], v3 = acc[mt][nt][3];
                if (addC) {
                    v0 += addC[o0]; v1 += addC[o0 + 1];
                    v2 += addC[o1]; v3 += addC[o1 + 1];
                }
                C[o0] = v0; C[o0 + 1] = v1;
                C[o1] = v2; C[o1 + 1] = v3;
            }
        }
    }
}

// =====================================================================
//  SIMT kernels
// =====================================================================
__device__ __forceinline__ float block_sum256(float v, float* red) {
    #pragma unroll
    for (int o = 16; o; o >>= 1) v += __shfl_down_sync(0xffffffffu, v, o);
    int lane = threadIdx.x & 31, wid = threadIdx.x >> 5;
    if (lane == 0) red[wid] = v;
    __syncthreads();
    if (wid == 0) {
        float w = (lane < 8) ? red[lane] : 0.f;
        #pragma unroll
        for (int o = 16; o; o >>= 1) w += __shfl_down_sync(0xffffffffu, w, o);
        if (lane == 0) red[0] = w;
    }
    __syncthreads();
    return red[0];
}

__global__ void __launch_bounds__(256)
rope_norm_kernel(float* __restrict__ q, hf* __restrict__ hhi,
                 const float* __restrict__ w, const float2* __restrict__ tab)
{
    int tok = blockIdx.x;
    int t = tok & (TSEQ - 1);
    __shared__ float row[DM];
    __shared__ float red[8];
    int tid = threadIdx.x;
    for (int i = tid; i < DM; i += 256) row[i] = q[(size_t)tok * DM + i];
    __syncthreads();

    float vals[4];
    float ss = 0.f;
    #pragma unroll
    for (int u = 0; u < 4; u++) {
        int d  = tid + u * 256;
        int hd = d & 63;
        int i  = hd & 31;
        float2 cs = tab[t * 32 + i];
        float v;
        if (hd < 32) { float q1 = row[d], q2 = row[d + 32]; v = q1 * cs.x - q2 * cs.y; }
        else         { float q2 = row[d], q1 = row[d - 32]; v = q2 * cs.x + q1 * cs.y; }
        vals[u] = v;
        ss += v * v;
    }
    float total = block_sum256(ss, red);
    float scale = rsqrtf(total * (1.f / DM) + 1e-5f);
    #pragma unroll
    for (int u = 0; u < 4; u++) {
        int d = tid + u * 256;
        q[(size_t)tok * DM + d] = vals[u];
        hhi[(size_t)tok * DM + d] = __float2half_rn(vals[u] * scale * w[d]);
    }
}

__global__ void __launch_bounds__(256)
dt_kernel(const float* __restrict__ zx, const float* __restrict__ dtb,
          float* __restrict__ dt)
{
    int idx = blockIdx.x * blockDim.x + threadIdx.x;
    if (idx >= NTOK * HS) return;
    int tok = idx >> 5, hh = idx & 31;
    float x = zx[(size_t)tok * DIP + (DIP - HS) + hh] + dtb[hh];
    float sp = (x > 20.f) ? x : log1pf(expf(x));
    dt[idx] = sp;
}

__global__ void __launch_bounds__(256)
conv_kernel(const float* __restrict__ zx, const float* __restrict__ cw,
            const float* __restrict__ cb, float* __restrict__ out,
            hf* __restrict__ bchi)
{
    int idx = blockIdx.x * blockDim.x + threadIdx.x;
    const int C4 = CONVD / 4;
    if (idx >= NTOK * C4) return;
    int tok = idx / C4, c4 = idx % C4;
    int ch = c4 * 4;
    int t = tok & (TSEQ - 1);

    float4 w0 = *(const float4*)(cw + (ch + 0) * 4);
    float4 w1 = *(const float4*)(cw + (ch + 1) * 4);
    float4 w2 = *(const float4*)(cw + (ch + 2) * 4);
    float4 w3 = *(const float4*)(cw + (ch + 3) * 4);

    float4 acc = *(const float4*)(cb + ch);
    #pragma unroll
    for (int k = 0; k < 4; k++) {
        int tt = t + k - 3;
        if (tt >= 0) {
            float4 v = *(const float4*)(zx + (size_t)(tok + k - 3) * DIP + DINNER + ch);
            float wk0 = (k == 0) ? w0.x : (k == 1) ? w0.y : (k == 2) ? w0.z : w0.w;
            float wk1 = (k == 0) ? w1.x : (k == 1) ? w1.y : (k == 2) ? w1.z : w1.w;
            float wk2 = (k == 0) ? w2.x : (k == 1) ? w2.y : (k == 2) ? w2.z : w2.w;
            float wk3 = (k == 0) ? w3.x : (k == 1) ? w3.y : (k == 2) ? w3.z : w3.w;
            acc.x += v.x * wk0; acc.y += v.y * wk1;
            acc.z += v.z * wk2; acc.w += v.w * wk3;
        }
    }
    float4 r;
    r.x = acc.x / (1.f + expf(-acc.x));
    r.y = acc.y / (1.f + expf(-acc.y));
    r.z = acc.z / (1.f + expf(-acc.z));
    r.w = acc.w / (1.f + expf(-acc.w));
    *(float4*)(out + (size_t)tok * CONVD + ch) = r;

    if (ch >= DINNER) {
        size_t o = (size_t)tok * 256 + (ch - DINNER);
        hf h[4];
        h[0] = __float2half_rn(r.x); h[1] = __float2half_rn(r.y);
        h[2] = __float2half_rn(r.z); h[3] = __float2half_rn(r.w);
        *(uint2*)(bchi + o) = *(uint2*)h;
    }
}

// =====================================================================
//  SSD part1: Y_diag via mma + chunk states via mma (unchanged from R14)
// =====================================================================
#define SSD1_SMEM (13320 * 4)

__global__ void __launch_bounds__(256)
ssd_part1(const float* __restrict__ xBC, const float* __restrict__ dt,
          const float* __restrict__ A_log, const float* __restrict__ G,
          const hf* __restrict__ Bhf,
          float* __restrict__ y, float* __restrict__ states,
          float* __restrict__ Asum, float* __restrict__ expAcs)
{
    extern __shared__ float dsm[];
    float* sAcs = dsm;
    float* sDt  = dsm + 256;
    float* sDec = dsm + 512;
    float* sESa = dsm + 768;
    float* warpsum = dsm + 1024;
    hf* sW  = (hf*)(dsm + 1032);     // [256][72]
    hf* sXT = (hf*)(dsm + 10248);    // [64][72]
    hf* sXD = (hf*)(dsm + 1032);     // [64][72]  (phase 2)
    hf* sBd = (hf*)(dsm + 3336);     // [64][136] (phase 2)

    int h = blockIdx.x, c = blockIdx.y, b = blockIdx.z;
    int l = threadIdx.x;
    int lane = l & 31, wid = l >> 5;
    int warp_m = wid & 3, warp_n = wid >> 2;
    int tok0 = b * TSEQ + c * CH;

    float dtl = dt[(size_t)(tok0 + l) * HS + h];
    float A   = -expf(A_log[h]);
    float adt = dtl * A;

    // inclusive scan of adt
    float v = adt;
    #pragma unroll
    for (int o = 1; o < 32; o <<= 1) {
        float u = __shfl_up_sync(0xffffffffu, v, o);
        if (lane >= o) v += u;
    }
    if (lane == 31) warpsum[wid] = v;
    __syncthreads();
    if (wid == 0) {
        float w = (lane < 8) ? warpsum[lane] : 0.f;
        #pragma unroll
        for (int o = 1; o < 8; o <<= 1) {
            float u = __shfl_up_sync(0xffffffffu, w, o);
            if (lane >= o) w += u;
        }
        if (lane < 8) warpsum[lane] = w;
    }
    __syncthreads();
    float acs   = v + ((wid > 0) ? warpsum[wid - 1] : 0.f);
    float total = warpsum[7];

    sAcs[l] = acs;
    sDt[l]  = dtl;
    sDec[l] = expf(total - acs);
    expAcs[(((size_t)(b * NC + c) * HS) + h) * CH + l] = expf(acs);
    if (l == 0) Asum[(b * HS + h) * NC + c] = total;
    __syncthreads();
    {
        int jt = l >> 6, s = l & 63;
        sESa[l] = __expf(sAcs[jt * 64 + 63] - sAcs[jt * 64 + s]);
    }

    const float* Gp = G + ((size_t)(b * NC + c)) * CH * CH;

    int a_r = (lane & 15), a_k = ((lane >> 4) << 3);
    int bg = lane >> 3, bq = lane & 7;
    int b_row = ((bg >> 1) << 3) + bq;
    int b_ko  = (bg & 1) << 3;

    // ---------------- phase 1: Y_diag via mma ----------------
    {
        float acc[2][8][4];
        #pragma unroll
        for (int mt = 0; mt < 2; mt++)
            #pragma unroll
            for (int nt = 0; nt < 8; nt++)
                #pragma unroll
                for (int e = 0; e < 4; e++) acc[mt][nt][e] = 0.f;

        int maxj = (wid * 32 + 31) >> 6;

        for (int j = 0; j < 4; j++) {
            int sbase = j * 64;
            __syncthreads();

            // stage xdt^T tile
            {
                int sp = l >> 2, q = l & 3;
                const float* xr = xBC + (size_t)(tok0 + sbase + sp) * CONVD + h * PD + q * 16;
                float dtv = sDt[sbase + sp];
                #pragma unroll
                for (int jj = 0; jj < 16; jj += 4) {
                    float4 vv = *(const float4*)(xr + jj);
                    sXT[(q * 16 + jj + 0) * 72 + sp] = __float2half_rn(vv.x * dtv);
                    sXT[(q * 16 + jj + 1) * 72 + sp] = __float2half_rn(vv.y * dtv);
                    sXT[(q * 16 + jj + 2) * 72 + sp] = __float2half_rn(vv.z * dtv);
                    sXT[(q * 16 + jj + 3) * 72 + sp] = __float2half_rn(vv.w * dtv);
                }
            }

            // build W row l
            int rel = l - sbase;
            if (rel >= 64) {
                float f = __expf(acs - sAcs[sbase + 63]);
                uint32_t* wr = (uint32_t*)(sW + l * 72);
                #pragma unroll 4
                for (int s = 0; s < 64; s += 2) {
                    float w0 = Gp[(size_t)(sbase + s) * CH + l] * (f * sESa[sbase + s]);
                    float w1 = Gp[(size_t)(sbase + s + 1) * CH + l] * (f * sESa[sbase + s + 1]);
                    wr[s >> 1] = packh2(w0, w1);
                }
            } else if (rel >= 0) {
                uint32_t* wr = (uint32_t*)(sW + l * 72);
                for (int s = 0; s < 64; s += 2) {
                    float w0 = (s     <= rel) ? Gp[(size_t)(sbase + s) * CH + l] * __expf(acs - sAcs[sbase + s]) : 0.f;
                    float w1 = (s + 1 <= rel) ? Gp[(size_t)(sbase + s + 1) * CH + l] * __expf(acs - sAcs[sbase + s + 1]) : 0.f;
                    wr[s >> 1] = packh2(w0, w1);
                }
            }
            __syncthreads();

            if (j <= maxj) {
                #pragma unroll
                for (int ks = 0; ks < 4; ks++) {
                    int k0 = ks * 16;
                    uint32_t a0[2][4];
                    #pragma unroll
                    for (int mt = 0; mt < 2; mt++) {
                        int ar = (wid * 32 + mt * 16 + a_r) * 72 + k0 + a_k;
                        ldsm_x4(a0[mt][0], a0[mt][1], a0[mt][2], a0[mt][3], sm32(&sW[ar]));
                    }
                    #pragma unroll
                    for (int ntp = 0; ntp < 4; ntp++) {
                        int br = (ntp * 16 + b_row) * 72 + k0 + b_ko;
                        uint32_t bb0, bb1, bb2, bb3;
                        ldsm_x4(bb0, bb1, bb2, bb3, sm32(&sXT[br]));
                        #pragma unroll
                        for (int mt = 0; mt < 2; mt++) {
                            mma16816h(acc[mt][ntp * 2 + 0], a0[mt], bb0, bb1);
                            mma16816h(acc[mt][ntp * 2 + 1], a0[mt], bb2, bb3);
                        }
                    }
                }
            }
        }

        // write Y_diag
        int tg = lane >> 2, tq = lane & 3;
        #pragma unroll
        for (int mt = 0; mt < 2; mt++) {
            int row = wid * 32 + mt * 16 + tg;
            #pragma unroll
            for (int nt = 0; nt < 8; nt++) {
                int p = nt * 8 + tq * 2;
                size_t o0 = (size_t)(tok0 + row) * DINNER + h * PD + p;
                size_t o1 = (size_t)(tok0 + row + 8) * DINNER + h * PD + p;
                y[o0] = acc[mt][nt][0]; y[o0 + 1] = acc[mt][nt][1];
                y[o1] = acc[mt][nt][2]; y[o1 + 1] = acc[mt][nt][3];
            }
        }
    }

    // ---------------- phase 2: chunk states via mma ----------------
    {
        float accs[8][4];
        #pragma unroll
        for (int nf = 0; nf < 8; nf++)
            #pragma unroll
            for (int e = 0; e < 4; e++) accs[nf][e] = 0.f;

        for (int j = 0; j < 4; j++) {
            int sbase = j * 64;
            __syncthreads();
            // stage A' = x*dt*dec transposed [p][l']
            {
                int sp = l >> 2, q = l & 3;
                const float* xr = xBC + (size_t)(tok0 + sbase + sp) * CONVD + h * PD + q * 16;
                float m = sDt[sbase + sp] * sDec[sbase + sp];
                #pragma unroll
                for (int jj = 0; jj < 16; jj += 4) {
                    float4 vv = *(const float4*)(xr + jj);
                    sXD[(q * 16 + jj + 0) * 72 + sp] = __float2half_rn(vv.x * m);
                    sXD[(q * 16 + jj + 1) * 72 + sp] = __float2half_rn(vv.y * m);
                    sXD[(q * 16 + jj + 2) * 72 + sp] = __float2half_rn(vv.z * m);
                    sXD[(q * 16 + jj + 3) * 72 + sp] = __float2half_rn(vv.w * m);
                }
            }
            // stage B tile [l'][n] (16 chunks of 8 halves per row)
            for (int i = l; i < 64 * 16; i += 256) {
                int r = i >> 4, cc = (i & 15) << 3;
                *(uint4*)&sBd[r * 136 + cc] =
                    *(const uint4*)(Bhf + (size_t)(tok0 + sbase + r) * 256 + cc);
            }
            __syncthreads();

            #pragma unroll
            for (int ks = 0; ks < 4; ks++) {
                int k0 = ks * 16;
                uint32_t aa[4];
                int ar = (warp_m * 16 + a_r) * 72 + k0 + a_k;
                ldsm_x4(aa[0], aa[1], aa[2], aa[3], sm32(&sXD[ar]));
                #pragma unroll
                for (int nf = 0; nf < 4; nf++) {
                    int nb = warp_n * 64 + nf * 16;
                    int addr = (k0 + ((bg & 1) << 3) + bq) * 136 + nb + ((bg >> 1) << 3);
                    uint32_t b0, b1, b2, b3;
                    ldsm_x4_t(b0, b1, b2, b3, sm32(&sBd[addr]));
                    mma16816h(accs[nf * 2 + 0], aa, b0, b1);
                    mma16816h(accs[nf * 2 + 1], aa, b2, b3);
                }
            }
        }

        // write states fragments
        int tg = lane >> 2, tq = lane & 3;
        float* sp = states + (((size_t)(b * NC + c) * HS) + h) * PD * DS;
        #pragma unroll
        for (int nf = 0; nf < 8; nf++) {
            int p0 = warp_m * 16 + tg;
            int n  = warp_n * 64 + nf * 8 + tq * 2;
            sp[(size_t)p0 * DS + n]           = accs[nf][0];
            sp[(size_t)p0 * DS + n + 1]       = accs[nf][1];
            sp[(size_t)(p0 + 8) * DS + n]     = accs[nf][2];
            sp[(size_t)(p0 + 8) * DS + n + 1] = accs[nf][3];
        }
    }
}

__global__ void __launch_bounds__(256)
ssd_prefix(float* __restrict__ states, const float* __restrict__ Asum)
{
    int h = blockIdx.x, b = blockIdx.y;
    float dec[NC];
    #pragma unroll
    for (int c = 0; c < NC; c++) dec[c] = expf(Asum[(b * HS + h) * NC + c]);
    for (int idx = threadIdx.x; idx < PD * DS; idx += blockDim.x) {
        float S = 0.f;
        #pragma unroll
        for (int c = 0; c < NC; c++) {
            size_t off = (((size_t)(b * NC + c) * HS) + h) * PD * DS + idx;
            float st = states[off];
            states[off] = S;
            S = dec[c] * S + st;
        }
    }
}

__global__ void __launch_bounds__(256)
ssd_part2(const float* __restrict__ xBC, const float* __restrict__ statesPrev,
          const float* __restrict__ expAcs, const float* __restrict__ D_param,
          float* __restrict__ y)
{
    int h = blockIdx.x, c = blockIdx.y, b = blockIdx.z;
    int l = threadIdx.x;
    int tok0 = b * TSEQ + c * CH;

    __shared__ float sS[DS][PD + 1];

    const float* Sp = statesPrev + (((size_t)(b * NC + c) * HS) + h) * PD * DS;
    for (int i = l; i < DS * PD; i += 256) {
        int n = i & (DS - 1), p = i >> 7;
        sS[n][p] = Sp[(size_t)p * DS + n];
    }
    __syncthreads();

    float acc[64];
    #pragma unroll
    for (int p = 0; p < 64; p++) acc[p] = 0.f;

    const float* Crow = xBC + (size_t)(tok0 + l) * CONVD + DINNER + DS;
    #pragma unroll 2
    for (int nt = 0; nt < 8; nt++) {
        int n0 = nt * 16;
        float cre[16];
        const float4* cp = (const float4*)(Crow + n0);
        #pragma unroll
        for (int q4 = 0; q4 < 4; q4++) {
            float4 vv = cp[q4];
            cre[q4 * 4 + 0] = vv.x; cre[q4 * 4 + 1] = vv.y;
            cre[q4 * 4 + 2] = vv.z; cre[q4 * 4 + 3] = vv.w;
        }
        #pragma unroll
        for (int nn = 0; nn < 16; nn++) {
            float cv = cre[nn];
            const float4* sr = (const float4*)sS[n0 + nn];
            #pragma unroll
            for (int p4 = 0; p4 < 16; p4++) {
                float4 sv = sr[p4];
                acc[p4 * 4 + 0] += cv * sv.x;
                acc[p4 * 4 + 1] += cv * sv.y;
                acc[p4 * 4 + 2] += cv * sv.z;
                acc[p4 * 4 + 3] += cv * sv.w;
            }
        }
    }

    float eA = expAcs[(((size_t)(b * NC + c) * HS) + h) * CH + l];
    float Dp = D_param[h];
    size_t ybase = (size_t)(tok0 + l) * DINNER + h * PD;
    size_t xbase = (size_t)(tok0 + l) * CONVD + h * PD;
    #pragma unroll
    for (int p = 0; p < 64; p++) {
        float xv = xBC[xbase + p];
        y[ybase + p] = y[ybase + p] + eA * acc[p] + Dp * xv;
    }
}

__global__ void __launch_bounds__(256)
gate_norm_kernel(const float* __restrict__ y, const float* __restrict__ zx,
                 const float* __restrict__ w, hf* __restrict__ yghi)
{
    int tok = blockIdx.x, tid = threadIdx.x;
    __shared__ float red[8];
    float g[8];
    float ss = 0.f;
    #pragma unroll
    for (int u = 0; u < 8; u++) {
        int d = tid + u * 256;
        float z  = zx[(size_t)tok * DIP + d];
        float yy = y[(size_t)tok * DINNER + d];
        float gv = yy * (z / (1.f + expf(-z)));
        g[u] = gv;
        ss += gv * gv;
    }
    float total = block_sum256(ss, red);
    float sc = rsqrtf(total * (1.f / DINNER) + 1e-5f);
    #pragma unroll
    for (int u = 0; u < 8; u++) {
        int d = tid + u * 256;
        yghi[(size_t)tok * DINNER + d] = __float2half_rn(g[u] * sc * w[d]);
    }
}

// ---------------- launch ----------------
extern "C" void kernel_launch(void* const* d_in, const int* in_sizes, int n_in,
                              void* d_out, int out_size)
{
    const float* x         = (const float*)d_in[0];
    const float* W_in      = (const float*)d_in[1];
    const float* W_z       = (const float*)d_in[2];
    const float* conv_w    = (const float*)d_in[3];
    const float* conv_b    = (const float*)d_in[4];
    const float* dt_bias   = (const float*)d_in[5];
    const float* A_log     = (const float*)d_in[6];
    const float* D_param   = (const float*)d_in[7];
    const float* norm_pre  = (const float*)d_in[8];
    const float* norm_gate = (const float*)d_in[9];
    const float* W_out     = (const float*)d_in[10];
    float* out = (float*)d_out;

    float* sc = nullptr;
    cudaGetSymbolAddress((void**)&sc, g_scratch);
    hf* XHI = (hf*)(sc + OFF_XHI);
    hf* WIH = (hf*)(sc + OFF_WIH);
    hf* WZH = (hf*)(sc + OFF_WZH);
    hf* WOH = (hf*)(sc + OFF_WOH);
    hf* HH  = (hf*)(sc + OFF_HH);
    hf* YGH = (hf*)(sc + OFF_YGH);
    hf* BCH = (hf*)(sc + OFF_BCH);
    float2* TAB = (float2*)(sc + OFF_TAB);

    cudaFuncSetAttribute(gemm_hf1, cudaFuncAttributeMaxDynamicSharedMemorySize, GEMM_SMEM);
    cudaFuncSetAttribute(ssd_part1, cudaFuncAttributeMaxDynamicSharedMemorySize, SSD1_SMEM);

    // 0) pre-computation (gemm #1 stays the 4th launch -> ncu profiles it)
    cvt_hi<<<(NTOK * DM / 4 + 255) / 256, 256>>>(x, XHI, NTOK * DM / 4);
    cvt_hi<<<(DM * DM / 4 + 255) / 256, 256>>>(W_in, WIH, DM * DM / 4);
    rope_tab_kernel<<<(TSEQ * 32 + 255) / 256, 256>>>(TAB);

    // 1) q = x @ W_in[:1024].T
    gemm_hf1<<<dim3(DM / BN, NTOK / BM, 1), 256, GEMM_SMEM>>>(
        XHI, WIH, sc + OFF_Q, nullptr, NTOK, DM, DM, DM, DM, DM, 0, 0, 0);

    cvt_hi<<<(DIP * DM / 4 + 255) / 256, 256>>>(W_z, WZH, DIP * DM / 4);
    cvt_hi<<<(DM * DINNER / 4 + 255) / 256, 256>>>(W_out, WOH, DM * DINNER / 4);

    // 2) rope + rmsnorm
    rope_norm_kernel<<<NTOK, 256>>>(sc + OFF_Q, HH, norm_pre, TAB);

    // 3) zxbcdt
    gemm_hf1<<<dim3((DIP + BN - 1) / BN, NTOK / BM, 1), 256, GEMM_SMEM>>>(
        HH, WZH, sc + OFF_ZX, nullptr, NTOK, DIP, DM, DM, DM, DIP, 0, 0, 0);

    // 4) dt
    dt_kernel<<<(NTOK * HS + 255) / 256, 256>>>(sc + OFF_ZX, dt_bias, sc + OFF_DT);

    // 5) conv + silu
    conv_kernel<<<(NTOK * (CONVD / 4) + 255) / 256, 256>>>(sc + OFF_ZX, conv_w, conv_b,
                                                           sc + OFF_XBC, BCH);

    // 6) G = B . C^T batched  (K = 128 -> KC = 2)
    gemm_hf1<<<dim3(CH / BN, CH / BM, 16), 256, GEMM_SMEM>>>(
        BCH, BCH + DS, sc + OFF_G, nullptr,
        CH, CH, DS, 256, 256, CH,
        (size_t)CH * 256, (size_t)CH * 256, (size_t)CH * CH);

    // 7) SSD part1
    ssd_part1<<<dim3(HS, NC, 2), 256, SSD1_SMEM>>>(
        sc + OFF_XBC, sc + OFF_DT, A_log, sc + OFF_G, BCH,
        sc + OFF_Y, sc + OFF_ST, sc + OFF_ASUM, sc + OFF_EACS);

    // 8) prefix
    ssd_prefix<<<dim3(HS, 2), 256>>>(sc + OFF_ST, sc + OFF_ASUM);

    // 9) part2
    ssd_part2<<<dim3(HS, NC, 2), 256>>>(
        sc + OFF_XBC, sc + OFF_ST, sc + OFF_EACS, D_param, sc + OFF_Y);

    // 10) gated rmsnorm
    gate_norm_kernel<<<NTOK, 256>>>(sc + OFF_Y, sc + OFF_ZX, norm_gate, YGH);

    // 11) out-proj + residual
    gemm_hf1<<<dim3(DM / BN, NTOK / BM, 1), 256, GEMM_SMEM>>>(
        YGH, WOH, out, sc + OFF_Q, NTOK, DM, DINNER, DINNER, DINNER, DM, 0, 0, 0);
}

// round 16
// speedup vs baseline: 1.1258x; 1.1258x over previous
#include <cuda_runtime.h>
#include <cuda_fp16.h>
#include <math.h>
#include <stdint.h>

// ---------------- problem constants ----------------
#define NTOK   4096          // N*T = 2*2048
#define TSEQ   2048
#define DM     1024          // d_model
#define DIP    4384          // d_in_proj
#define DINNER 2048
#define CONVD  2304          // d_inner + 2*d_state
#define HS     32            // ssm heads
#define PD     64            // headdim
#define DS     128           // d_state
#define CH     256           // chunk
#define NC     8             // chunks per sequence

// ---------------- scratch layout (floats) ----------------
#define OFF_Q    0ull                 // 4096*1024   roped q (residual)
#define OFF_ZX   8388608ull           // 4096*4384   zxbcdt
#define OFF_XBC  26345472ull          // 4096*2304   conv+silu output
#define OFF_DT   35782656ull          // 4096*32     softplus dt
#define OFF_G    35913728ull          // 16*256*256  G^T per (b,c): [s][l]
#define OFF_ST   36962304ull          // 16*32*64*128 chunk states -> states_prev
#define OFF_ASUM 41156608ull          // 2*32*8      chunk A sums
#define OFF_EACS 41157120ull          // 16*32*256   exp(Acs)
#define OFF_Y    41288192ull          // 4096*2048   y
// fp16 arrays (offsets in floats; 1 float = 2 halves)
#define OFF_XHI  58065408ull
#define OFF_WIH  62259712ull
#define OFF_WZH  63308288ull
#define OFF_WOH  67797504ull
#define OFF_HH   69894656ull
#define OFF_YGH  74088960ull
#define OFF_BCH  82477568ull
#define OFF_TAB  83526144ull          // 2048*32 float2 rope table
#define SCRATCH_FLOATS 83657216ull

__device__ float g_scratch[SCRATCH_FLOATS];

typedef __half hf;

// =====================================================================
//  helpers
// =====================================================================
__device__ __forceinline__ uint32_t sm32(const void* p) {
    return (uint32_t)__cvta_generic_to_shared(p);
}
__device__ __forceinline__ void ldsm_x4(uint32_t& r0, uint32_t& r1, uint32_t& r2, uint32_t& r3,
                                        uint32_t a) {
    asm volatile("ldmatrix.sync.aligned.m8n8.x4.shared.b16 {%0,%1,%2,%3}, [%4];"
                 : "=r"(r0), "=r"(r1), "=r"(r2), "=r"(r3) : "r"(a));
}
__device__ __forceinline__ void ldsm_x4_t(uint32_t& r0, uint32_t& r1, uint32_t& r2, uint32_t& r3,
                                          uint32_t a) {
    asm volatile("ldmatrix.sync.aligned.m8n8.x4.trans.shared.b16 {%0,%1,%2,%3}, [%4];"
                 : "=r"(r0), "=r"(r1), "=r"(r2), "=r"(r3) : "r"(a));
}
__device__ __forceinline__ void mma16816h(float* c, const uint32_t* a, uint32_t b0, uint32_t b1) {
    asm volatile(
        "mma.sync.aligned.m16n8k16.row.col.f32.f16.f16.f32 "
        "{%0,%1,%2,%3}, {%4,%5,%6,%7}, {%8,%9}, {%0,%1,%2,%3};"
        : "+f"(c[0]), "+f"(c[1]), "+f"(c[2]), "+f"(c[3])
        : "r"(a[0]), "r"(a[1]), "r"(a[2]), "r"(a[3]), "r"(b0), "r"(b1));
}
__device__ __forceinline__ void cp16(uint32_t s, const void* g, int bytes) {
    asm volatile("cp.async.cg.shared.global [%0], [%1], 16, %2;"
                 :: "r"(s), "l"(g), "r"(bytes));
}
__device__ __forceinline__ uint32_t packh2(float a, float b) {
    __half2 h = __floats2half2_rn(a, b);
    return *(uint32_t*)&h;
}

// ---------------- rope sin/cos table ----------------
__global__ void __launch_bounds__(256)
rope_tab_kernel(float2* __restrict__ tab)
{
    int idx = blockIdx.x * blockDim.x + threadIdx.x;
    if (idx >= TSEQ * 32) return;
    int t = idx >> 5, j = idx & 31;
    float inv = exp2f(-(float)(2 * j) * (1.f / 64.f) * 13.287712379549449f);
    float c, s;
    sincosf((float)t * inv, &s, &c);
    tab[idx] = make_float2(c, s);
}

// fp32 -> fp16 (rn)
__global__ void __launch_bounds__(256)
cvt_hi(const float* __restrict__ in, hf* __restrict__ hi, int n4)
{
    int i = blockIdx.x * blockDim.x + threadIdx.x;
    if (i >= n4) return;
    float4 v = ((const float4*)in)[i];
    hf h[4];
    h[0] = __float2half_rn(v.x); h[1] = __float2half_rn(v.y);
    h[2] = __float2half_rn(v.z); h[3] = __float2half_rn(v.w);
    ((uint2*)hi)[i] = *(uint2*)h;
}

// =====================================================================
//  3-stage pipelined single-product fp16 GEMM, BK=32 (R14 config — best)
// =====================================================================
#define BM 128
#define BN 128
#define BK 32
#define LDK 40
#define MAT  (BM * LDK)
#define STGX (2 * MAT)
#define NSTAGE 3
#define GEMM_SMEM (NSTAGE * STGX * 2)

__global__ void __launch_bounds__(256, 2)
gemm_hf1(const hf* __restrict__ Ah, const hf* __restrict__ Bh,
         float* __restrict__ C, const float* __restrict__ addC,
         int M, int N, int K, int lda, int ldb, int ldc,
         size_t bsA, size_t bsB, size_t bsC)
{
    extern __shared__ hf sm[];

    Ah += bsA * blockIdx.z;
    Bh += bsB * blockIdx.z;
    C  += bsC * blockIdx.z;

    int tid = threadIdx.x, lane = tid & 31, wid = tid >> 5;
    int warp_m = wid & 3, warp_n = wid >> 2;
    int m0 = blockIdx.y * BM, n0 = blockIdx.x * BN;

    float acc[2][8][4];
    #pragma unroll
    for (int mt = 0; mt < 2; mt++)
        #pragma unroll
        for (int nt = 0; nt < 8; nt++)
            #pragma unroll
            for (int e = 0; e < 4; e++) acc[mt][nt][e] = 0.f;

    const int KC = K >> 5;

    int r0 = tid >> 2,         k80 = (tid & 3) << 3;
    int r1 = (tid + 256) >> 2;
    bool bv0 = (n0 + r0) < N, bv1 = (n0 + r1) < N;
    int br0 = bv0 ? r0 : 0, br1 = bv1 ? r1 : 0;

    auto load_stage = [&](int kc, int st) {
        hf* base = sm + st * STGX;
        uint32_t s0 = sm32(base + r0 * LDK + k80);
        uint32_t s1 = sm32(base + r1 * LDK + k80);
        size_t a0 = (size_t)(m0 + r0) * lda + kc + k80;
        size_t a1 = (size_t)(m0 + r1) * lda + kc + k80;
        size_t b0 = (size_t)(n0 + br0) * ldb + kc + k80;
        size_t b1 = (size_t)(n0 + br1) * ldb + kc + k80;
        cp16(s0,           Ah + a0, 16);
        cp16(s1,           Ah + a1, 16);
        cp16(s0 + 2 * MAT, Bh + b0, bv0 ? 16 : 0);
        cp16(s1 + 2 * MAT, Bh + b1, bv1 ? 16 : 0);
    };

    int a_r = (lane & 15), a_k = ((lane >> 4) << 3);
    int bg = lane >> 3, bq = lane & 7;
    int b_row = ((bg >> 1) << 3) + bq;
    int b_ko  = (bg & 1) << 3;

    load_stage(0, 0);
    asm volatile("cp.async.commit_group;");
    load_stage(32, 1);
    asm volatile("cp.async.commit_group;");

    for (int c = 0; c < KC; c++) {
        if (c + 1 < KC) asm volatile("cp.async.wait_group 1;");
        else            asm volatile("cp.async.wait_group 0;");
        __syncthreads();

        if (c + 2 < KC) {
            load_stage((c + 2) << 5, (c + 2) % NSTAGE);
            asm volatile("cp.async.commit_group;");
        }

        hf* base = sm + (c % NSTAGE) * STGX;
        hf* sA = base;
        hf* sB = base + MAT;

        #pragma unroll
        for (int ks = 0; ks < 2; ks++) {
            int k0 = ks * 16;
            uint32_t ah[2][4];
            #pragma unroll
            for (int mt = 0; mt < 2; mt++) {
                int ar = (warp_m * 32 + mt * 16 + a_r) * LDK + k0 + a_k;
                ldsm_x4(ah[mt][0], ah[mt][1], ah[mt][2], ah[mt][3], sm32(&sA[ar]));
            }
            #pragma unroll
            for (int ntp = 0; ntp < 4; ntp++) {
                int br = (warp_n * 64 + ntp * 16 + b_row) * LDK + k0 + b_ko;
                uint32_t b0, b1, b2, b3;
                ldsm_x4(b0, b1, b2, b3, sm32(&sB[br]));
                #pragma unroll
                for (int mt = 0; mt < 2; mt++) {
                    mma16816h(acc[mt][ntp * 2 + 0], ah[mt], b0, b1);
                    mma16816h(acc[mt][ntp * 2 + 1], ah[mt], b2, b3);
                }
            }
        }
    }

    int tg = lane >> 2, tq = lane & 3;
    #pragma unroll
    for (int mt = 0; mt < 2; mt++) {
        int m = m0 + warp_m * 32 + mt * 16 + tg;
        #pragma unroll
        for (int nt = 0; nt < 8; nt++) {
            int n = n0 + warp_n * 64 + nt * 8 + tq * 2;
            if (n < N) {
                size_t o0 = (size_t)m * ldc + n;
                size_t o1 = (size_t)(m + 8) * ldc + n;
                float v0 = acc[mt][nt][0], v1 = acc[mt][nt][1];
                float v2 = acc[mt][nt][2], v3 = acc[mt][nt][3];
                if (addC) {
                    v0 += addC[o0]; v1 += addC[o0 + 1];
                    v2 += addC[o1]; v3 += addC[o1 + 1];
                }
                C[o0] = v0; C[o0 + 1] = v1;
                C[o1] = v2; C[o1 + 1] = v3;
            }
        }
    }
}

// =====================================================================
//  SIMT kernels
// =====================================================================
__device__ __forceinline__ float block_sum256(float v, float* red) {
    #pragma unroll
    for (int o = 16; o; o >>= 1) v += __shfl_down_sync(0xffffffffu, v, o);
    int lane = threadIdx.x & 31, wid = threadIdx.x >> 5;
    if (lane == 0) red[wid] = v;
    __syncthreads();
    if (wid == 0) {
        float w = (lane < 8) ? red[lane] : 0.f;
        #pragma unroll
        for (int o = 16; o; o >>= 1) w += __shfl_down_sync(0xffffffffu, w, o);
        if (lane == 0) red[0] = w;
    }
    __syncthreads();
    return red[0];
}

__global__ void __launch_bounds__(256)
rope_norm_kernel(float* __restrict__ q, hf* __restrict__ hhi,
                 const float* __restrict__ w, const float2* __restrict__ tab)
{
    int tok = blockIdx.x;
    int t = tok & (TSEQ - 1);
    __shared__ float row[DM];
    __shared__ float red[8];
    int tid = threadIdx.x;
    for (int i = tid; i < DM; i += 256) row[i] = q[(size_t)tok * DM + i];
    __syncthreads();

    float vals[4];
    float ss = 0.f;
    #pragma unroll
    for (int u = 0; u < 4; u++) {
        int d  = tid + u * 256;
        int hd = d & 63;
        int i  = hd & 31;
        float2 cs = tab[t * 32 + i];
        float v;
        if (hd < 32) { float q1 = row[d], q2 = row[d + 32]; v = q1 * cs.x - q2 * cs.y; }
        else         { float q2 = row[d], q1 = row[d - 32]; v = q2 * cs.x + q1 * cs.y; }
        vals[u] = v;
        ss += v * v;
    }
    float total = block_sum256(ss, red);
    float scale = rsqrtf(total * (1.f / DM) + 1e-5f);
    #pragma unroll
    for (int u = 0; u < 4; u++) {
        int d = tid + u * 256;
        q[(size_t)tok * DM + d] = vals[u];
        hhi[(size_t)tok * DM + d] = __float2half_rn(vals[u] * scale * w[d]);
    }
}

__global__ void __launch_bounds__(256)
dt_kernel(const float* __restrict__ zx, const float* __restrict__ dtb,
          float* __restrict__ dt)
{
    int idx = blockIdx.x * blockDim.x + threadIdx.x;
    if (idx >= NTOK * HS) return;
    int tok = idx >> 5, hh = idx & 31;
    float x = zx[(size_t)tok * DIP + (DIP - HS) + hh] + dtb[hh];
    float sp = (x > 20.f) ? x : log1pf(expf(x));
    dt[idx] = sp;
}

// conv + silu, 4 tokens x 4 channels per thread (7-row halo load)
__global__ void __launch_bounds__(256)
conv_kernel(const float* __restrict__ zx, const float* __restrict__ cw,
            const float* __restrict__ cb, float* __restrict__ out,
            hf* __restrict__ bchi)
{
    const int C4 = CONVD / 4;               // 576
    const int NG = NTOK / 4;                // 1024 token groups
    int idx = blockIdx.x * blockDim.x + threadIdx.x;
    if (idx >= NG * C4) return;
    int g = idx / C4, c4 = idx % C4;
    int ch = c4 * 4;
    int tok0 = g * 4;
    int t0 = tok0 & (TSEQ - 1);

    float4 w0 = *(const float4*)(cw + (ch + 0) * 4);
    float4 w1 = *(const float4*)(cw + (ch + 1) * 4);
    float4 w2 = *(const float4*)(cw + (ch + 2) * 4);
    float4 w3 = *(const float4*)(cw + (ch + 3) * 4);
    float4 bias = *(const float4*)(cb + ch);

    // rows[r] = zx row for token tok0 + r - 3  (r = 0..6)
    float4 rows[7];
    #pragma unroll
    for (int r = 0; r < 7; r++) {
        int t = t0 + r - 3;
        rows[r] = (t >= 0 && r < 7)
            ? ((t0 + r - 3 >= 0 && t >= 0)
               ? *(const float4*)(zx + (size_t)(tok0 + r - 3) * DIP + DINNER + ch)
               : make_float4(0.f, 0.f, 0.f, 0.f))
            : make_float4(0.f, 0.f, 0.f, 0.f);
        if (t < 0) rows[r] = make_float4(0.f, 0.f, 0.f, 0.f);
    }

    #pragma unroll
    for (int j = 0; j < 4; j++) {          // token tok0 + j
        float4 acc = bias;
        #pragma unroll
        for (int k = 0; k < 4; k++) {      // tap k uses rows[j + k]
            float4 v = rows[j + k];
            float wk0 = (k == 0) ? w0.x : (k == 1) ? w0.y : (k == 2) ? w0.z : w0.w;
            float wk1 = (k == 0) ? w1.x : (k == 1) ? w1.y : (k == 2) ? w1.z : w1.w;
            float wk2 = (k == 0) ? w2.x : (k == 1) ? w2.y : (k == 2) ? w2.z : w2.w;
            float wk3 = (k == 0) ? w3.x : (k == 1) ? w3.y : (k == 2) ? w3.z : w3.w;
            acc.x += v.x * wk0; acc.y += v.y * wk1;
            acc.z += v.z * wk2; acc.w += v.w * wk3;
        }
        float4 r;
        r.x = acc.x / (1.f + expf(-acc.x));
        r.y = acc.y / (1.f + expf(-acc.y));
        r.z = acc.z / (1.f + expf(-acc.z));
        r.w = acc.w / (1.f + expf(-acc.w));
        *(float4*)(out + (size_t)(tok0 + j) * CONVD + ch) = r;

        if (ch >= DINNER) {
            size_t o = (size_t)(tok0 + j) * 256 + (ch - DINNER);
            hf h[4];
            h[0] = __float2half_rn(r.x); h[1] = __float2half_rn(r.y);
            h[2] = __float2half_rn(r.z); h[3] = __float2half_rn(r.w);
            *(uint2*)(bchi + o) = *(uint2*)h;
        }
    }
}

// =====================================================================
//  SSD part1: Y_diag via mma + chunk states via mma
// =====================================================================
#define SSD1_SMEM (13320 * 4)

__global__ void __launch_bounds__(256)
ssd_part1(const float* __restrict__ xBC, const float* __restrict__ dt,
          const float* __restrict__ A_log, const float* __restrict__ G,
          const hf* __restrict__ Bhf,
          float* __restrict__ y, float* __restrict__ states,
          float* __restrict__ Asum, float* __restrict__ expAcs)
{
    extern __shared__ float dsm[];
    float* sAcs = dsm;
    float* sDt  = dsm + 256;
    float* sDec = dsm + 512;
    float* sESa = dsm + 768;
    float* warpsum = dsm + 1024;
    hf* sW  = (hf*)(dsm + 1032);     // [256][72]
    hf* sXT = (hf*)(dsm + 10248);    // [64][72]
    hf* sXD = (hf*)(dsm + 1032);     // [64][72]  (phase 2)
    hf* sBd = (hf*)(dsm + 3336);     // [64][136] (phase 2)

    int h = blockIdx.x, c = blockIdx.y, b = blockIdx.z;
    int l = threadIdx.x;
    int lane = l & 31, wid = l >> 5;
    int warp_m = wid & 3, warp_n = wid >> 2;
    int tok0 = b * TSEQ + c * CH;

    float dtl = dt[(size_t)(tok0 + l) * HS + h];
    float A   = -expf(A_log[h]);
    float adt = dtl * A;

    // inclusive scan of adt
    float v = adt;
    #pragma unroll
    for (int o = 1; o < 32; o <<= 1) {
        float u = __shfl_up_sync(0xffffffffu, v, o);
        if (lane >= o) v += u;
    }
    if (lane == 31) warpsum[wid] = v;
    __syncthreads();
    if (wid == 0) {
        float w = (lane < 8) ? warpsum[lane] : 0.f;
        #pragma unroll
        for (int o = 1; o < 8; o <<= 1) {
            float u = __shfl_up_sync(0xffffffffu, w, o);
            if (lane >= o) w += u;
        }
        if (lane < 8) warpsum[lane] = w;
    }
    __syncthreads();
    float acs   = v + ((wid > 0) ? warpsum[wid - 1] : 0.f);
    float total = warpsum[7];

    sAcs[l] = acs;
    sDt[l]  = dtl;
    sDec[l] = expf(total - acs);
    expAcs[(((size_t)(b * NC + c) * HS) + h) * CH + l] = expf(acs);
    if (l == 0) Asum[(b * HS + h) * NC + c] = total;
    __syncthreads();
    {
        int jt = l >> 6, s = l & 63;
        sESa[l] = __expf(sAcs[jt * 64 + 63] - sAcs[jt * 64 + s]);
    }

    const float* Gp = G + ((size_t)(b * NC + c)) * CH * CH;

    int a_r = (lane & 15), a_k = ((lane >> 4) << 3);
    int bg = lane >> 3, bq = lane & 7;
    int b_row = ((bg >> 1) << 3) + bq;
    int b_ko  = (bg & 1) << 3;

    // ---------------- phase 1: Y_diag via mma ----------------
    {
        float acc[2][8][4];
        #pragma unroll
        for (int mt = 0; mt < 2; mt++)
            #pragma unroll
            for (int nt = 0; nt < 8; nt++)
                #pragma unroll
                for (int e = 0; e < 4; e++) acc[mt][nt][e] = 0.f;

        int maxj = (wid * 32 + 31) >> 6;

        for (int j = 0; j < 4; j++) {
            int sbase = j * 64;
            __syncthreads();

            // stage xdt^T tile
            {
                int sp = l >> 2, q = l & 3;
                const float* xr = xBC + (size_t)(tok0 + sbase + sp) * CONVD + h * PD + q * 16;
                float dtv = sDt[sbase + sp];
                #pragma unroll
                for (int jj = 0; jj < 16; jj += 4) {
                    float4 vv = *(const float4*)(xr + jj);
                    sXT[(q * 16 + jj + 0) * 72 + sp] = __float2half_rn(vv.x * dtv);
                    sXT[(q * 16 + jj + 1) * 72 + sp] = __float2half_rn(vv.y * dtv);
                    sXT[(q * 16 + jj + 2) * 72 + sp] = __float2half_rn(vv.z * dtv);
                    sXT[(q * 16 + jj + 3) * 72 + sp] = __float2half_rn(vv.w * dtv);
                }
            }

            // build W row l
            int rel = l - sbase;
            if (rel >= 64) {
                float f = __expf(acs - sAcs[sbase + 63]);
                uint32_t* wr = (uint32_t*)(sW + l * 72);
                #pragma unroll 4
                for (int s = 0; s < 64; s += 2) {
                    float w0 = Gp[(size_t)(sbase + s) * CH + l] * (f * sESa[sbase + s]);
                    float w1 = Gp[(size_t)(sbase + s + 1) * CH + l] * (f * sESa[sbase + s + 1]);
                    wr[s >> 1] = packh2(w0, w1);
                }
            } else if (rel >= 0) {
                uint32_t* wr = (uint32_t*)(sW + l * 72);
                for (int s = 0; s < 64; s += 2) {
                    float w0 = (s     <= rel) ? Gp[(size_t)(sbase + s) * CH + l] * __expf(acs - sAcs[sbase + s]) : 0.f;
                    float w1 = (s + 1 <= rel) ? Gp[(size_t)(sbase + s + 1) * CH + l] * __expf(acs - sAcs[sbase + s + 1]) : 0.f;
                    wr[s >> 1] = packh2(w0, w1);
                }
            }
            __syncthreads();

            if (j <= maxj) {
                #pragma unroll
                for (int ks = 0; ks < 4; ks++) {
                    int k0 = ks * 16;
                    uint32_t a0[2][4];
                    #pragma unroll
                    for (int mt = 0; mt < 2; mt++) {
                        int ar = (wid * 32 + mt * 16 + a_r) * 72 + k0 + a_k;
                        ldsm_x4(a0[mt][0], a0[mt][1], a0[mt][2], a0[mt][3], sm32(&sW[ar]));
                    }
                    #pragma unroll
                    for (int ntp = 0; ntp < 4; ntp++) {
                        int br = (ntp * 16 + b_row) * 72 + k0 + b_ko;
                        uint32_t bb0, bb1, bb2, bb3;
                        ldsm_x4(bb0, bb1, bb2, bb3, sm32(&sXT[br]));
                        #pragma unroll
                        for (int mt = 0; mt < 2; mt++) {
                            mma16816h(acc[mt][ntp * 2 + 0], a0[mt], bb0, bb1);
                            mma16816h(acc[mt][ntp * 2 + 1], a0[mt], bb2, bb3);
                        }
                    }
                }
            }
        }

        // write Y_diag
        int tg = lane >> 2, tq = lane & 3;
        #pragma unroll
        for (int mt = 0; mt < 2; mt++) {
            int row = wid * 32 + mt * 16 + tg;
            #pragma unroll
            for (int nt = 0; nt < 8; nt++) {
                int p = nt * 8 + tq * 2;
                size_t o0 = (size_t)(tok0 + row) * DINNER + h * PD + p;
                size_t o1 = (size_t)(tok0 + row + 8) * DINNER + h * PD + p;
                y[o0] = acc[mt][nt][0]; y[o0 + 1] = acc[mt][nt][1];
                y[o1] = acc[mt][nt][2]; y[o1 + 1] = acc[mt][nt][3];
            }
        }
    }

    // ---------------- phase 2: chunk states via mma ----------------
    {
        float accs[8][4];
        #pragma unroll
        for (int nf = 0; nf < 8; nf++)
            #pragma unroll
            for (int e = 0; e < 4; e++) accs[nf][e] = 0.f;

        for (int j = 0; j < 4; j++) {
            int sbase = j * 64;
            __syncthreads();
            // stage A' = x*dt*dec transposed [p][l']
            {
                int sp = l >> 2, q = l & 3;
                const float* xr = xBC + (size_t)(tok0 + sbase + sp) * CONVD + h * PD + q * 16;
                float m = sDt[sbase + sp] * sDec[sbase + sp];
                #pragma unroll
                for (int jj = 0; jj < 16; jj += 4) {
                    float4 vv = *(const float4*)(xr + jj);
                    sXD[(q * 16 + jj + 0) * 72 + sp] = __float2half_rn(vv.x * m);
                    sXD[(q * 16 + jj + 1) * 72 + sp] = __float2half_rn(vv.y * m);
                    sXD[(q * 16 + jj + 2) * 72 + sp] = __float2half_rn(vv.z * m);
                    sXD[(q * 16 + jj + 3) * 72 + sp] = __float2half_rn(vv.w * m);
                }
            }
            // stage B tile [l'][n] (16 chunks of 8 halves per row)
            for (int i = l; i < 64 * 16; i += 256) {
                int r = i >> 4, cc = (i & 15) << 3;
                *(uint4*)&sBd[r * 136 + cc] =
                    *(const uint4*)(Bhf + (size_t)(tok0 + sbase + r) * 256 + cc);
            }
            __syncthreads();

            #pragma unroll
            for (int ks = 0; ks < 4; ks++) {
                int k0 = ks * 16;
                uint32_t aa[4];
                int ar = (warp_m * 16 + a_r) * 72 + k0 + a_k;
                ldsm_x4(aa[0], aa[1], aa[2], aa[3], sm32(&sXD[ar]));
                #pragma unroll
                for (int nf = 0; nf < 4; nf++) {
                    int nb = warp_n * 64 + nf * 16;
                    int addr = (k0 + ((bg & 1) << 3) + bq) * 136 + nb + ((bg >> 1) << 3);
                    uint32_t b0, b1, b2, b3;
                    ldsm_x4_t(b0, b1, b2, b3, sm32(&sBd[addr]));
                    mma16816h(accs[nf * 2 + 0], aa, b0, b1);
                    mma16816h(accs[nf * 2 + 1], aa, b2, b3);
                }
            }
        }

        // write states fragments
        int tg = lane >> 2, tq = lane & 3;
        float* sp = states + (((size_t)(b * NC + c) * HS) + h) * PD * DS;
        #pragma unroll
        for (int nf = 0; nf < 8; nf++) {
            int p0 = warp_m * 16 + tg;
            int n  = warp_n * 64 + nf * 8 + tq * 2;
            sp[(size_t)p0 * DS + n]           = accs[nf][0];
            sp[(size_t)p0 * DS + n + 1]       = accs[nf][1];
            sp[(size_t)(p0 + 8) * DS + n]     = accs[nf][2];
            sp[(size_t)(p0 + 8) * DS + n + 1] = accs[nf][3];
        }
    }
}

__global__ void __launch_bounds__(256)
ssd_prefix(float* __restrict__ states, const float* __restrict__ Asum)
{
    int h = blockIdx.x, b = blockIdx.y;
    float dec[NC];
    #pragma unroll
    for (int c = 0; c < NC; c++) dec[c] = expf(Asum[(b * HS + h) * NC + c]);
    for (int idx = threadIdx.x; idx < PD * DS; idx += blockDim.x) {
        float S = 0.f;
        #pragma unroll
        for (int c = 0; c < NC; c++) {
            size_t off = (((size_t)(b * NC + c) * HS) + h) * PD * DS + idx;
            float st = states[off];
            states[off] = S;
            S = dec[c] * S + st;
        }
    }
}

__global__ void __launch_bounds__(256)
ssd_part2(const float* __restrict__ xBC, const float* __restrict__ statesPrev,
          const float* __restrict__ expAcs, const float* __restrict__ D_param,
          float* __restrict__ y)
{
    int h = blockIdx.x, c = blockIdx.y, b = blockIdx.z;
    int l = threadIdx.x;
    int tok0 = b * TSEQ + c * CH;

    __shared__ float sS[DS][PD + 1];

    const float* Sp = statesPrev + (((size_t)(b * NC + c) * HS) + h) * PD * DS;
    for (int i = l; i < DS * PD; i += 256) {
        int n = i & (DS - 1), p = i >> 7;
        sS[n][p] = Sp[(size_t)p * DS + n];
    }
    __syncthreads();

    float acc[64];
    #pragma unroll
    for (int p = 0; p < 64; p++) acc[p] = 0.f;

    const float* Crow = xBC + (size_t)(tok0 + l) * CONVD + DINNER + DS;
    #pragma unroll 2
    for (int nt = 0; nt < 8; nt++) {
        int n0 = nt * 16;
        float cre[16];
        const float4* cp = (const float4*)(Crow + n0);
        #pragma unroll
        for (int q4 = 0; q4 < 4; q4++) {
            float4 vv = cp[q4];
            cre[q4 * 4 + 0] = vv.x; cre[q4 * 4 + 1] = vv.y;
            cre[q4 * 4 + 2] = vv.z; cre[q4 * 4 + 3] = vv.w;
        }
        #pragma unroll
        for (int nn = 0; nn < 16; nn++) {
            float cv = cre[nn];
            const float4* sr = (const float4*)sS[n0 + nn];
            #pragma unroll
            for (int p4 = 0; p4 < 16; p4++) {
                float4 sv = sr[p4];
                acc[p4 * 4 + 0] += cv * sv.x;
                acc[p4 * 4 + 1] += cv * sv.y;
                acc[p4 * 4 + 2] += cv * sv.z;
                acc[p4 * 4 + 3] += cv * sv.w;
            }
        }
    }

    float eA = expAcs[(((size_t)(b * NC + c) * HS) + h) * CH + l];
    float Dp = D_param[h];
    size_t ybase = (size_t)(tok0 + l) * DINNER + h * PD;
    size_t xbase = (size_t)(tok0 + l) * CONVD + h * PD;
    #pragma unroll
    for (int p = 0; p < 64; p++) {
        float xv = xBC[xbase + p];
        y[ybase + p] = y[ybase + p] + eA * acc[p] + Dp * xv;
    }
}

__global__ void __launch_bounds__(256)
gate_norm_kernel(const float* __restrict__ y, const float* __restrict__ zx,
                 const float* __restrict__ w, hf* __restrict__ yghi)
{
    int tok = blockIdx.x, tid = threadIdx.x;
    __shared__ float red[8];
    float g[8];
    float ss = 0.f;
    #pragma unroll
    for (int u = 0; u < 8; u++) {
        int d = tid + u * 256;
        float z  = zx[(size_t)tok * DIP + d];
        float yy = y[(size_t)tok * DINNER + d];
        float gv = yy * (z / (1.f + expf(-z)));
        g[u] = gv;
        ss += gv * gv;
    }
    float total = block_sum256(ss, red);
    float sc = rsqrtf(total * (1.f / DINNER) + 1e-5f);
    #pragma unroll
    for (int u = 0; u < 8; u++) {
        int d = tid + u * 256;
        yghi[(size_t)tok * DINNER + d] = __float2half_rn(g[u] * sc * w[d]);
    }
}

// ---------------- launch ----------------
extern "C" void kernel_launch(void* const* d_in, const int* in_sizes, int n_in,
                              void* d_out, int out_size)
{
    const float* x         = (const float*)d_in[0];
    const float* W_in      = (const float*)d_in[1];
    const float* W_z       = (const float*)d_in[2];
    const float* conv_w    = (const float*)d_in[3];
    const float* conv_b    = (const float*)d_in[4];
    const float* dt_bias   = (const float*)d_in[5];
    const float* A_log     = (const float*)d_in[6];
    const float* D_param   = (const float*)d_in[7];
    const float* norm_pre  = (const float*)d_in[8];
    const float* norm_gate = (const float*)d_in[9];
    const float* W_out     = (const float*)d_in[10];
    float* out = (float*)d_out;

    float* sc = nullptr;
    cudaGetSymbolAddress((void**)&sc, g_scratch);
    hf* XHI = (hf*)(sc + OFF_XHI);
    hf* WIH = (hf*)(sc + OFF_WIH);
    hf* WZH = (hf*)(sc + OFF_WZH);
    hf* WOH = (hf*)(sc + OFF_WOH);
    hf* HH  = (hf*)(sc + OFF_HH);
    hf* YGH = (hf*)(sc + OFF_YGH);
    hf* BCH = (hf*)(sc + OFF_BCH);
    float2* TAB = (float2*)(sc + OFF_TAB);

    cudaFuncSetAttribute(gemm_hf1, cudaFuncAttributeMaxDynamicSharedMemorySize, GEMM_SMEM);
    cudaFuncSetAttribute(ssd_part1, cudaFuncAttributeMaxDynamicSharedMemorySize, SSD1_SMEM);

    // 0) pre-computation (gemm #1 stays the 4th launch -> ncu profiles it)
    cvt_hi<<<(NTOK * DM / 4 + 255) / 256, 256>>>(x, XHI, NTOK * DM / 4);
    cvt_hi<<<(DM * DM / 4 + 255) / 256, 256>>>(W_in, WIH, DM * DM / 4);
    rope_tab_kernel<<<(TSEQ * 32 + 255) / 256, 256>>>(TAB);

    // 1) q = x @ W_in[:1024].T
    gemm_hf1<<<dim3(DM / BN, NTOK / BM, 1), 256, GEMM_SMEM>>>(
        XHI, WIH, sc + OFF_Q, nullptr, NTOK, DM, DM, DM, DM, DM, 0, 0, 0);

    cvt_hi<<<(DIP * DM / 4 + 255) / 256, 256>>>(W_z, WZH, DIP * DM / 4);
    cvt_hi<<<(DM * DINNER / 4 + 255) / 256, 256>>>(W_out, WOH, DM * DINNER / 4);

    // 2) rope + rmsnorm
    rope_norm_kernel<<<NTOK, 256>>>(sc + OFF_Q, HH, norm_pre, TAB);

    // 3) zxbcdt
    gemm_hf1<<<dim3((DIP + BN - 1) / BN, NTOK / BM, 1), 256, GEMM_SMEM>>>(
        HH, WZH, sc + OFF_ZX, nullptr, NTOK, DIP, DM, DM, DM, DIP, 0, 0, 0);

    // 4) dt
    dt_kernel<<<(NTOK * HS + 255) / 256, 256>>>(sc + OFF_ZX, dt_bias, sc + OFF_DT);

    // 5) conv + silu (4 tokens/thread)
    conv_kernel<<<((NTOK / 4) * (CONVD / 4) + 255) / 256, 256>>>(
        sc + OFF_ZX, conv_w, conv_b, sc + OFF_XBC, BCH);

    // 6) G = B . C^T batched
    gemm_hf1<<<dim3(CH / BN, CH / BM, 16), 256, GEMM_SMEM>>>(
        BCH, BCH + DS, sc + OFF_G, nullptr,
        CH, CH, DS, 256, 256, CH,
        (size_t)CH * 256, (size_t)CH * 256, (size_t)CH * CH);

    // 7) SSD part1
    ssd_part1<<<dim3(HS, NC, 2), 256, SSD1_SMEM>>>(
        sc + OFF_XBC, sc + OFF_DT, A_log, sc + OFF_G, BCH,
        sc + OFF_Y, sc + OFF_ST, sc + OFF_ASUM, sc + OFF_EACS);

    // 8) prefix
    ssd_prefix<<<dim3(HS, 2), 256>>>(sc + OFF_ST, sc + OFF_ASUM);

    // 9) part2
    ssd_part2<<<dim3(HS, NC, 2), 256>>>(
        sc + OFF_XBC, sc + OFF_ST, sc + OFF_EACS, D_param, sc + OFF_Y);

    // 10) gated rmsnorm
    gate_norm_kernel<<<NTOK, 256>>>(sc + OFF_Y, sc + OFF_ZX, norm_gate, YGH);

    // 11) out-proj + residual
    gemm_hf1<<<dim3(DM / BN, NTOK / BM, 1), 256, GEMM_SMEM>>>(
        YGH, WOH, out, sc + OFF_Q, NTOK, DM, DINNER, DINNER, DINNER, DM, 0, 0, 0);
}

// round 17
// speedup vs baseline: 1.4885x; 1.3222x over previous
#include <cuda_runtime.h>
#include <cuda_fp16.h>
#include <math.h>
#include <stdint.h>

// ---------------- problem constants ----------------
#define NTOK   4096          // N*T = 2*2048
#define TSEQ   2048
#define DM     1024          // d_model
#define DIP    4384          // d_in_proj
#define DINNER 2048
#define CONVD  2304          // d_inner + 2*d_state
#define HS     32            // ssm heads
#define PD     64            // headdim
#define DS     128           // d_state
#define CH     256           // chunk
#define NC     8             // chunks per sequence

// ---------------- scratch layout (floats) ----------------
#define OFF_Q    0ull                 // 4096*1024   roped q (residual)
#define OFF_ZX   8388608ull           // 4096*4384   zxbcdt
#define OFF_XBC  26345472ull          // 4096*2304   conv+silu output
#define OFF_DT   35782656ull          // 4096*32     softplus dt
#define OFF_G    35913728ull          // 16*256*256  G^T per (b,c): [s][l]
#define OFF_ST   36962304ull          // 16*32*64*128 chunk states -> states_prev
#define OFF_ASUM 41156608ull          // 2*32*8      chunk A sums
#define OFF_EACS 41157120ull          // 16*32*256   exp(Acs)
#define OFF_Y    41288192ull          // 4096*2048   y
// fp16 arrays (offsets in floats; 1 float = 2 halves)
#define OFF_XHI  58065408ull
#define OFF_WIH  62259712ull
#define OFF_WZH  63308288ull
#define OFF_WOH  67797504ull
#define OFF_HH   69894656ull
#define OFF_YGH  74088960ull
#define OFF_BCH  82477568ull
#define OFF_TAB  83526144ull          // 2048*32 float2 rope table
#define SCRATCH_FLOATS 83657216ull

__device__ float g_scratch[SCRATCH_FLOATS];

typedef __half hf;

// =====================================================================
//  helpers
// =====================================================================
__device__ __forceinline__ uint32_t sm32(const void* p) {
    return (uint32_t)__cvta_generic_to_shared(p);
}
__device__ __forceinline__ void ldsm_x4(uint32_t& r0, uint32_t& r1, uint32_t& r2, uint32_t& r3,
                                        uint32_t a) {
    asm volatile("ldmatrix.sync.aligned.m8n8.x4.shared.b16 {%0,%1,%2,%3}, [%4];"
                 : "=r"(r0), "=r"(r1), "=r"(r2), "=r"(r3) : "r"(a));
}
__device__ __forceinline__ void ldsm_x4_t(uint32_t& r0, uint32_t& r1, uint32_t& r2, uint32_t& r3,
                                          uint32_t a) {
    asm volatile("ldmatrix.sync.aligned.m8n8.x4.trans.shared.b16 {%0,%1,%2,%3}, [%4];"
                 : "=r"(r0), "=r"(r1), "=r"(r2), "=r"(r3) : "r"(a));
}
__device__ __forceinline__ void mma16816h(float* c, const uint32_t* a, uint32_t b0, uint32_t b1) {
    asm volatile(
        "mma.sync.aligned.m16n8k16.row.col.f32.f16.f16.f32 "
        "{%0,%1,%2,%3}, {%4,%5,%6,%7}, {%8,%9}, {%0,%1,%2,%3};"
        : "+f"(c[0]), "+f"(c[1]), "+f"(c[2]), "+f"(c[3])
        : "r"(a[0]), "r"(a[1]), "r"(a[2]), "r"(a[3]), "r"(b0), "r"(b1));
}
__device__ __forceinline__ void cp16(uint32_t s, const void* g, int bytes) {
    asm volatile("cp.async.cg.shared.global [%0], [%1], 16, %2;"
                 :: "r"(s), "l"(g), "r"(bytes));
}
__device__ __forceinline__ uint32_t packh2(float a, float b) {
    __half2 h = __floats2half2_rn(a, b);
    return *(uint32_t*)&h;
}

// ---------------- rope sin/cos table ----------------
__global__ void __launch_bounds__(256)
rope_tab_kernel(float2* __restrict__ tab)
{
    int idx = blockIdx.x * blockDim.x + threadIdx.x;
    if (idx >= TSEQ * 32) return;
    int t = idx >> 5, j = idx & 31;
    float inv = exp2f(-(float)(2 * j) * (1.f / 64.f) * 13.287712379549449f);
    float c, s;
    sincosf((float)t * inv, &s, &c);
    tab[idx] = make_float2(c, s);
}

// fp32 -> fp16 (rn)
__global__ void __launch_bounds__(256)
cvt_hi(const float* __restrict__ in, hf* __restrict__ hi, int n4)
{
    int i = blockIdx.x * blockDim.x + threadIdx.x;
    if (i >= n4) return;
    float4 v = ((const float4*)in)[i];
    hf h[4];
    h[0] = __float2half_rn(v.x); h[1] = __float2half_rn(v.y);
    h[2] = __float2half_rn(v.z); h[3] = __float2half_rn(v.w);
    ((uint2*)hi)[i] = *(uint2*)h;
}

// =====================================================================
//  3-stage pipelined single-product fp16 GEMM, BK=32 (best config)
// =====================================================================
#define BM 128
#define BN 128
#define BK 32
#define LDK 40
#define MAT  (BM * LDK)
#define STGX (2 * MAT)
#define NSTAGE 3
#define GEMM_SMEM (NSTAGE * STGX * 2)

__global__ void __launch_bounds__(256, 2)
gemm_hf1(const hf* __restrict__ Ah, const hf* __restrict__ Bh,
         float* __restrict__ C, const float* __restrict__ addC,
         int M, int N, int K, int lda, int ldb, int ldc,
         size_t bsA, size_t bsB, size_t bsC)
{
    extern __shared__ hf sm[];

    Ah += bsA * blockIdx.z;
    Bh += bsB * blockIdx.z;
    C  += bsC * blockIdx.z;

    int tid = threadIdx.x, lane = tid & 31, wid = tid >> 5;
    int warp_m = wid & 3, warp_n = wid >> 2;
    int m0 = blockIdx.y * BM, n0 = blockIdx.x * BN;

    float acc[2][8][4];
    #pragma unroll
    for (int mt = 0; mt < 2; mt++)
        #pragma unroll
        for (int nt = 0; nt < 8; nt++)
            #pragma unroll
            for (int e = 0; e < 4; e++) acc[mt][nt][e] = 0.f;

    const int KC = K >> 5;

    int r0 = tid >> 2,         k80 = (tid & 3) << 3;
    int r1 = (tid + 256) >> 2;
    bool bv0 = (n0 + r0) < N, bv1 = (n0 + r1) < N;
    int br0 = bv0 ? r0 : 0, br1 = bv1 ? r1 : 0;

    auto load_stage = [&](int kc, int st) {
        hf* base = sm + st * STGX;
        uint32_t s0 = sm32(base + r0 * LDK + k80);
        uint32_t s1 = sm32(base + r1 * LDK + k80);
        size_t a0 = (size_t)(m0 + r0) * lda + kc + k80;
        size_t a1 = (size_t)(m0 + r1) * lda + kc + k80;
        size_t b0 = (size_t)(n0 + br0) * ldb + kc + k80;
        size_t b1 = (size_t)(n0 + br1) * ldb + kc + k80;
        cp16(s0,           Ah + a0, 16);
        cp16(s1,           Ah + a1, 16);
        cp16(s0 + 2 * MAT, Bh + b0, bv0 ? 16 : 0);
        cp16(s1 + 2 * MAT, Bh + b1, bv1 ? 16 : 0);
    };

    int a_r = (lane & 15), a_k = ((lane >> 4) << 3);
    int bg = lane >> 3, bq = lane & 7;
    int b_row = ((bg >> 1) << 3) + bq;
    int b_ko  = (bg & 1) << 3;

    load_stage(0, 0);
    asm volatile("cp.async.commit_group;");
    load_stage(32, 1);
    asm volatile("cp.async.commit_group;");

    for (int c = 0; c < KC; c++) {
        if (c + 1 < KC) asm volatile("cp.async.wait_group 1;");
        else            asm volatile("cp.async.wait_group 0;");
        __syncthreads();

        if (c + 2 < KC) {
            load_stage((c + 2) << 5, (c + 2) % NSTAGE);
            asm volatile("cp.async.commit_group;");
        }

        hf* base = sm + (c % NSTAGE) * STGX;
        hf* sA = base;
        hf* sB = base + MAT;

        #pragma unroll
        for (int ks = 0; ks < 2; ks++) {
            int k0 = ks * 16;
            uint32_t ah[2][4];
            #pragma unroll
            for (int mt = 0; mt < 2; mt++) {
                int ar = (warp_m * 32 + mt * 16 + a_r) * LDK + k0 + a_k;
                ldsm_x4(ah[mt][0], ah[mt][1], ah[mt][2], ah[mt][3], sm32(&sA[ar]));
            }
            #pragma unroll
            for (int ntp = 0; ntp < 4; ntp++) {
                int br = (warp_n * 64 + ntp * 16 + b_row) * LDK + k0 + b_ko;
                uint32_t b0, b1, b2, b3;
                ldsm_x4(b0, b1, b2, b3, sm32(&sB[br]));
                #pragma unroll
                for (int mt = 0; mt < 2; mt++) {
                    mma16816h(acc[mt][ntp * 2 + 0], ah[mt], b0, b1);
                    mma16816h(acc[mt][ntp * 2 + 1], ah[mt], b2, b3);
                }
            }
        }
    }

    int tg = lane >> 2, tq = lane & 3;
    #pragma unroll
    for (int mt = 0; mt < 2; mt++) {
        int m = m0 + warp_m * 32 + mt * 16 + tg;
        #pragma unroll
        for (int nt = 0; nt < 8; nt++) {
            int n = n0 + warp_n * 64 + nt * 8 + tq * 2;
            if (n < N) {
                size_t o0 = (size_t)m * ldc + n;
                size_t o1 = (size_t)(m + 8) * ldc + n;
                float v0 = acc[mt][nt][0], v1 = acc[mt][nt][1];
                float v2 = acc[mt][nt][2], v3 = acc[mt][nt][3];
                if (addC) {
                    v0 += addC[o0]; v1 += addC[o0 + 1];
                    v2 += addC[o1]; v3 += addC[o1 + 1];
                }
                C[o0] = v0; C[o0 + 1] = v1;
                C[o1] = v2; C[o1 + 1] = v3;
            }
        }
    }
}

// =====================================================================
//  SIMT kernels
// =====================================================================
__device__ __forceinline__ float block_sum256(float v, float* red) {
    #pragma unroll
    for (int o = 16; o; o >>= 1) v += __shfl_down_sync(0xffffffffu, v, o);
    int lane = threadIdx.x & 31, wid = threadIdx.x >> 5;
    if (lane == 0) red[wid] = v;
    __syncthreads();
    if (wid == 0) {
        float w = (lane < 8) ? red[lane] : 0.f;
        #pragma unroll
        for (int o = 16; o; o >>= 1) w += __shfl_down_sync(0xffffffffu, w, o);
        if (lane == 0) red[0] = w;
    }
    __syncthreads();
    return red[0];
}

__global__ void __launch_bounds__(256)
rope_norm_kernel(float* __restrict__ q, hf* __restrict__ hhi,
                 const float* __restrict__ w, const float2* __restrict__ tab)
{
    int tok = blockIdx.x;
    int t = tok & (TSEQ - 1);
    __shared__ float row[DM];
    __shared__ float red[8];
    int tid = threadIdx.x;
    for (int i = tid; i < DM; i += 256) row[i] = q[(size_t)tok * DM + i];
    __syncthreads();

    float vals[4];
    float ss = 0.f;
    #pragma unroll
    for (int u = 0; u < 4; u++) {
        int d  = tid + u * 256;
        int hd = d & 63;
        int i  = hd & 31;
        float2 cs = tab[t * 32 + i];
        float v;
        if (hd < 32) { float q1 = row[d], q2 = row[d + 32]; v = q1 * cs.x - q2 * cs.y; }
        else         { float q2 = row[d], q1 = row[d - 32]; v = q2 * cs.x + q1 * cs.y; }
        vals[u] = v;
        ss += v * v;
    }
    float total = block_sum256(ss, red);
    float scale = rsqrtf(total * (1.f / DM) + 1e-5f);
    #pragma unroll
    for (int u = 0; u < 4; u++) {
        int d = tid + u * 256;
        q[(size_t)tok * DM + d] = vals[u];
        hhi[(size_t)tok * DM + d] = __float2half_rn(vals[u] * scale * w[d]);
    }
}

__global__ void __launch_bounds__(256)
dt_kernel(const float* __restrict__ zx, const float* __restrict__ dtb,
          float* __restrict__ dt)
{
    int idx = blockIdx.x * blockDim.x + threadIdx.x;
    if (idx >= NTOK * HS) return;
    int tok = idx >> 5, hh = idx & 31;
    float x = zx[(size_t)tok * DIP + (DIP - HS) + hh] + dtb[hh];
    float sp = (x > 20.f) ? x : log1pf(expf(x));
    dt[idx] = sp;
}

// conv + silu, 4 tokens x 4 channels per thread (7-row halo load)
__global__ void __launch_bounds__(256)
conv_kernel(const float* __restrict__ zx, const float* __restrict__ cw,
            const float* __restrict__ cb, float* __restrict__ out,
            hf* __restrict__ bchi)
{
    const int C4 = CONVD / 4;               // 576
    const int NG = NTOK / 4;                // 1024 token groups
    int idx = blockIdx.x * blockDim.x + threadIdx.x;
    if (idx >= NG * C4) return;
    int g = idx / C4, c4 = idx % C4;
    int ch = c4 * 4;
    int tok0 = g * 4;
    int t0 = tok0 & (TSEQ - 1);

    float4 w0 = *(const float4*)(cw + (ch + 0) * 4);
    float4 w1 = *(const float4*)(cw + (ch + 1) * 4);
    float4 w2 = *(const float4*)(cw + (ch + 2) * 4);
    float4 w3 = *(const float4*)(cw + (ch + 3) * 4);
    float4 bias = *(const float4*)(cb + ch);

    float4 rows[7];
    #pragma unroll
    for (int r = 0; r < 7; r++) {
        int t = t0 + r - 3;
        if (t >= 0)
            rows[r] = *(const float4*)(zx + (size_t)(tok0 + r - 3) * DIP + DINNER + ch);
        else
            rows[r] = make_float4(0.f, 0.f, 0.f, 0.f);
    }

    #pragma unroll
    for (int j = 0; j < 4; j++) {
        float4 acc = bias;
        #pragma unroll
        for (int k = 0; k < 4; k++) {
            float4 v = rows[j + k];
            float wk0 = (k == 0) ? w0.x : (k == 1) ? w0.y : (k == 2) ? w0.z : w0.w;
            float wk1 = (k == 0) ? w1.x : (k == 1) ? w1.y : (k == 2) ? w1.z : w1.w;
            float wk2 = (k == 0) ? w2.x : (k == 1) ? w2.y : (k == 2) ? w2.z : w2.w;
            float wk3 = (k == 0) ? w3.x : (k == 1) ? w3.y : (k == 2) ? w3.z : w3.w;
            acc.x += v.x * wk0; acc.y += v.y * wk1;
            acc.z += v.z * wk2; acc.w += v.w * wk3;
        }
        float4 r;
        r.x = acc.x / (1.f + expf(-acc.x));
        r.y = acc.y / (1.f + expf(-acc.y));
        r.z = acc.z / (1.f + expf(-acc.z));
        r.w = acc.w / (1.f + expf(-acc.w));
        *(float4*)(out + (size_t)(tok0 + j) * CONVD + ch) = r;

        if (ch >= DINNER) {
            size_t o = (size_t)(tok0 + j) * 256 + (ch - DINNER);
            hf h[4];
            h[0] = __float2half_rn(r.x); h[1] = __float2half_rn(r.y);
            h[2] = __float2half_rn(r.z); h[3] = __float2half_rn(r.w);
            *(uint2*)(bchi + o) = *(uint2*)h;
        }
    }
}

// =====================================================================
//  SSD part1: Y_diag via mma + chunk states via mma (unchanged from R16)
// =====================================================================
#define SSD1_SMEM (13320 * 4)

__global__ void __launch_bounds__(256)
ssd_part1(const float* __restrict__ xBC, const float* __restrict__ dt,
          const float* __restrict__ A_log, const float* __restrict__ G,
          const hf* __restrict__ Bhf,
          float* __restrict__ y, float* __restrict__ states,
          float* __restrict__ Asum, float* __restrict__ expAcs)
{
    extern __shared__ float dsm[];
    float* sAcs = dsm;
    float* sDt  = dsm + 256;
    float* sDec = dsm + 512;
    float* sESa = dsm + 768;
    float* warpsum = dsm + 1024;
    hf* sW  = (hf*)(dsm + 1032);     // [256][72]
    hf* sXT = (hf*)(dsm + 10248);    // [64][72]
    hf* sXD = (hf*)(dsm + 1032);     // [64][72]  (phase 2)
    hf* sBd = (hf*)(dsm + 3336);     // [64][136] (phase 2)

    int h = blockIdx.x, c = blockIdx.y, b = blockIdx.z;
    int l = threadIdx.x;
    int lane = l & 31, wid = l >> 5;
    int warp_m = wid & 3, warp_n = wid >> 2;
    int tok0 = b * TSEQ + c * CH;

    float dtl = dt[(size_t)(tok0 + l) * HS + h];
    float A   = -expf(A_log[h]);
    float adt = dtl * A;

    float v = adt;
    #pragma unroll
    for (int o = 1; o < 32; o <<= 1) {
        float u = __shfl_up_sync(0xffffffffu, v, o);
        if (lane >= o) v += u;
    }
    if (lane == 31) warpsum[wid] = v;
    __syncthreads();
    if (wid == 0) {
        float w = (lane < 8) ? warpsum[lane] : 0.f;
        #pragma unroll
        for (int o = 1; o < 8; o <<= 1) {
            float u = __shfl_up_sync(0xffffffffu, w, o);
            if (lane >= o) w += u;
        }
        if (lane < 8) warpsum[lane] = w;
    }
    __syncthreads();
    float acs   = v + ((wid > 0) ? warpsum[wid - 1] : 0.f);
    float total = warpsum[7];

    sAcs[l] = acs;
    sDt[l]  = dtl;
    sDec[l] = expf(total - acs);
    expAcs[(((size_t)(b * NC + c) * HS) + h) * CH + l] = expf(acs);
    if (l == 0) Asum[(b * HS + h) * NC + c] = total;
    __syncthreads();
    {
        int jt = l >> 6, s = l & 63;
        sESa[l] = __expf(sAcs[jt * 64 + 63] - sAcs[jt * 64 + s]);
    }

    const float* Gp = G + ((size_t)(b * NC + c)) * CH * CH;

    int a_r = (lane & 15), a_k = ((lane >> 4) << 3);
    int bg = lane >> 3, bq = lane & 7;
    int b_row = ((bg >> 1) << 3) + bq;
    int b_ko  = (bg & 1) << 3;

    // ---------------- phase 1: Y_diag via mma ----------------
    {
        float acc[2][8][4];
        #pragma unroll
        for (int mt = 0; mt < 2; mt++)
            #pragma unroll
            for (int nt = 0; nt < 8; nt++)
                #pragma unroll
                for (int e = 0; e < 4; e++) acc[mt][nt][e] = 0.f;

        int maxj = (wid * 32 + 31) >> 6;

        for (int j = 0; j < 4; j++) {
            int sbase = j * 64;
            __syncthreads();

            {
                int sp = l >> 2, q = l & 3;
                const float* xr = xBC + (size_t)(tok0 + sbase + sp) * CONVD + h * PD + q * 16;
                float dtv = sDt[sbase + sp];
                #pragma unroll
                for (int jj = 0; jj < 16; jj += 4) {
                    float4 vv = *(const float4*)(xr + jj);
                    sXT[(q * 16 + jj + 0) * 72 + sp] = __float2half_rn(vv.x * dtv);
                    sXT[(q * 16 + jj + 1) * 72 + sp] = __float2half_rn(vv.y * dtv);
                    sXT[(q * 16 + jj + 2) * 72 + sp] = __float2half_rn(vv.z * dtv);
                    sXT[(q * 16 + jj + 3) * 72 + sp] = __float2half_rn(vv.w * dtv);
                }
            }

            int rel = l - sbase;
            if (rel >= 64) {
                float f = __expf(acs - sAcs[sbase + 63]);
                uint32_t* wr = (uint32_t*)(sW + l * 72);
                #pragma unroll 4
                for (int s = 0; s < 64; s += 2) {
                    float w0 = Gp[(size_t)(sbase + s) * CH + l] * (f * sESa[sbase + s]);
                    float w1 = Gp[(size_t)(sbase + s + 1) * CH + l] * (f * sESa[sbase + s + 1]);
                    wr[s >> 1] = packh2(w0, w1);
                }
            } else if (rel >= 0) {
                uint32_t* wr = (uint32_t*)(sW + l * 72);
                for (int s = 0; s < 64; s += 2) {
                    float w0 = (s     <= rel) ? Gp[(size_t)(sbase + s) * CH + l] * __expf(acs - sAcs[sbase + s]) : 0.f;
                    float w1 = (s + 1 <= rel) ? Gp[(size_t)(sbase + s + 1) * CH + l] * __expf(acs - sAcs[sbase + s + 1]) : 0.f;
                    wr[s >> 1] = packh2(w0, w1);
                }
            }
            __syncthreads();

            if (j <= maxj) {
                #pragma unroll
                for (int ks = 0; ks < 4; ks++) {
                    int k0 = ks * 16;
                    uint32_t a0[2][4];
                    #pragma unroll
                    for (int mt = 0; mt < 2; mt++) {
                        int ar = (wid * 32 + mt * 16 + a_r) * 72 + k0 + a_k;
                        ldsm_x4(a0[mt][0], a0[mt][1], a0[mt][2], a0[mt][3], sm32(&sW[ar]));
                    }
                    #pragma unroll
                    for (int ntp = 0; ntp < 4; ntp++) {
                        int br = (ntp * 16 + b_row) * 72 + k0 + b_ko;
                        uint32_t bb0, bb1, bb2, bb3;
                        ldsm_x4(bb0, bb1, bb2, bb3, sm32(&sXT[br]));
                        #pragma unroll
                        for (int mt = 0; mt < 2; mt++) {
                            mma16816h(acc[mt][ntp * 2 + 0], a0[mt], bb0, bb1);
                            mma16816h(acc[mt][ntp * 2 + 1], a0[mt], bb2, bb3);
                        }
                    }
                }
            }
        }

        int tg = lane >> 2, tq = lane & 3;
        #pragma unroll
        for (int mt = 0; mt < 2; mt++) {
            int row = wid * 32 + mt * 16 + tg;
            #pragma unroll
            for (int nt = 0; nt < 8; nt++) {
                int p = nt * 8 + tq * 2;
                size_t o0 = (size_t)(tok0 + row) * DINNER + h * PD + p;
                size_t o1 = (size_t)(tok0 + row + 8) * DINNER + h * PD + p;
                y[o0] = acc[mt][nt][0]; y[o0 + 1] = acc[mt][nt][1];
                y[o1] = acc[mt][nt][2]; y[o1 + 1] = acc[mt][nt][3];
            }
        }
    }

    // ---------------- phase 2: chunk states via mma ----------------
    {
        float accs[8][4];
        #pragma unroll
        for (int nf = 0; nf < 8; nf++)
            #pragma unroll
            for (int e = 0; e < 4; e++) accs[nf][e] = 0.f;

        for (int j = 0; j < 4; j++) {
            int sbase = j * 64;
            __syncthreads();
            {
                int sp = l >> 2, q = l & 3;
                const float* xr = xBC + (size_t)(tok0 + sbase + sp) * CONVD + h * PD + q * 16;
                float m = sDt[sbase + sp] * sDec[sbase + sp];
                #pragma unroll
                for (int jj = 0; jj < 16; jj += 4) {
                    float4 vv = *(const float4*)(xr + jj);
                    sXD[(q * 16 + jj + 0) * 72 + sp] = __float2half_rn(vv.x * m);
                    sXD[(q * 16 + jj + 1) * 72 + sp] = __float2half_rn(vv.y * m);
                    sXD[(q * 16 + jj + 2) * 72 + sp] = __float2half_rn(vv.z * m);
                    sXD[(q * 16 + jj + 3) * 72 + sp] = __float2half_rn(vv.w * m);
                }
            }
            for (int i = l; i < 64 * 16; i += 256) {
                int r = i >> 4, cc = (i & 15) << 3;
                *(uint4*)&sBd[r * 136 + cc] =
                    *(const uint4*)(Bhf + (size_t)(tok0 + sbase + r) * 256 + cc);
            }
            __syncthreads();

            #pragma unroll
            for (int ks = 0; ks < 4; ks++) {
                int k0 = ks * 16;
                uint32_t aa[4];
                int ar = (warp_m * 16 + a_r) * 72 + k0 + a_k;
                ldsm_x4(aa[0], aa[1], aa[2], aa[3], sm32(&sXD[ar]));
                #pragma unroll
                for (int nf = 0; nf < 4; nf++) {
                    int nb = warp_n * 64 + nf * 16;
                    int addr = (k0 + ((bg & 1) << 3) + bq) * 136 + nb + ((bg >> 1) << 3);
                    uint32_t b0, b1, b2, b3;
                    ldsm_x4_t(b0, b1, b2, b3, sm32(&sBd[addr]));
                    mma16816h(accs[nf * 2 + 0], aa, b0, b1);
                    mma16816h(accs[nf * 2 + 1], aa, b2, b3);
                }
            }
        }

        int tg = lane >> 2, tq = lane & 3;
        float* sp = states + (((size_t)(b * NC + c) * HS) + h) * PD * DS;
        #pragma unroll
        for (int nf = 0; nf < 8; nf++) {
            int p0 = warp_m * 16 + tg;
            int n  = warp_n * 64 + nf * 8 + tq * 2;
            sp[(size_t)p0 * DS + n]           = accs[nf][0];
            sp[(size_t)p0 * DS + n + 1]       = accs[nf][1];
            sp[(size_t)(p0 + 8) * DS + n]     = accs[nf][2];
            sp[(size_t)(p0 + 8) * DS + n + 1] = accs[nf][3];
        }
    }
}

__global__ void __launch_bounds__(256)
ssd_prefix(float* __restrict__ states, const float* __restrict__ Asum)
{
    int h = blockIdx.x, b = blockIdx.y;
    float dec[NC];
    #pragma unroll
    for (int c = 0; c < NC; c++) dec[c] = expf(Asum[(b * HS + h) * NC + c]);
    for (int idx = threadIdx.x; idx < PD * DS; idx += blockDim.x) {
        float S = 0.f;
        #pragma unroll
        for (int c = 0; c < NC; c++) {
            size_t off = (((size_t)(b * NC + c) * HS) + h) * PD * DS + idx;
            float st = states[off];
            states[off] = S;
            S = dec[c] * S + st;
        }
    }
}

// =====================================================================
//  SSD part2 via mma: y += eA * (C . S_prev^T) + D*x
//  A = C[l][n] fp16 (from BC array, offset DS); B = S_prev[p][n] fp16-staged
// =====================================================================
__global__ void __launch_bounds__(256)
ssd_part2(const float* __restrict__ xBC, const float* __restrict__ statesPrev,
          const float* __restrict__ expAcs, const float* __restrict__ D_param,
          const hf* __restrict__ BChf, float* __restrict__ y)
{
    __shared__ hf sC[256 * 72];      // C tile: [l][n'] (n-tile of 64)
    __shared__ hf sS[64 * 72];       // S tile: [p][n']
    __shared__ float sEA[256];

    int h = blockIdx.x, c = blockIdx.y, b = blockIdx.z;
    int l = threadIdx.x;
    int lane = l & 31, wid = l >> 5;
    int tok0 = b * TSEQ + c * CH;

    sEA[l] = expAcs[(((size_t)(b * NC + c) * HS) + h) * CH + l];

    const float* Sp = statesPrev + (((size_t)(b * NC + c) * HS) + h) * PD * DS;

    int a_r = (lane & 15), a_k = ((lane >> 4) << 3);
    int bg = lane >> 3, bq = lane & 7;
    int b_row = ((bg >> 1) << 3) + bq;
    int b_ko  = (bg & 1) << 3;

    float acc[2][8][4];
    #pragma unroll
    for (int mt = 0; mt < 2; mt++)
        #pragma unroll
        for (int nt = 0; nt < 8; nt++)
            #pragma unroll
            for (int e = 0; e < 4; e++) acc[mt][nt][e] = 0.f;

    for (int ntile = 0; ntile < 2; ntile++) {
        int n0 = ntile * 64;
        __syncthreads();
        // stage C [256 rows][64 cols] from fp16 BC (C at col DS + n0)
        for (int i = l; i < 256 * 8; i += 256) {
            int r = i >> 3, cc = (i & 7) << 3;
            *(uint4*)&sC[r * 72 + cc] =
                *(const uint4*)(BChf + (size_t)(tok0 + r) * 256 + DS + n0 + cc);
        }
        // stage S [64 p][64 cols] fp32 -> fp16
        for (int i = l; i < 64 * 16; i += 256) {
            int r = i >> 4, cc = (i & 15) << 2;
            float4 vv = *(const float4*)(Sp + (size_t)r * DS + n0 + cc);
            uint2 pk;
            pk.x = packh2(vv.x, vv.y);
            pk.y = packh2(vv.z, vv.w);
            *(uint2*)&sS[r * 72 + cc] = pk;
        }
        __syncthreads();

        #pragma unroll
        for (int ks = 0; ks < 4; ks++) {
            int k0 = ks * 16;
            uint32_t a0[2][4];
            #pragma unroll
            for (int mt = 0; mt < 2; mt++) {
                int ar = (wid * 32 + mt * 16 + a_r) * 72 + k0 + a_k;
                ldsm_x4(a0[mt][0], a0[mt][1], a0[mt][2], a0[mt][3], sm32(&sC[ar]));
            }
            #pragma unroll
            for (int ntp = 0; ntp < 4; ntp++) {
                int br = (ntp * 16 + b_row) * 72 + k0 + b_ko;
                uint32_t bb0, bb1, bb2, bb3;
                ldsm_x4(bb0, bb1, bb2, bb3, sm32(&sS[br]));
                #pragma unroll
                for (int mt = 0; mt < 2; mt++) {
                    mma16816h(acc[mt][ntp * 2 + 0], a0[mt], bb0, bb1);
                    mma16816h(acc[mt][ntp * 2 + 1], a0[mt], bb2, bb3);
                }
            }
        }
    }

    // epilogue: y += eA[row]*acc + D*x
    float Dp = D_param[h];
    int tg = lane >> 2, tq = lane & 3;
    #pragma unroll
    for (int mt = 0; mt < 2; mt++) {
        int row = wid * 32 + mt * 16 + tg;
        float e0 = sEA[row], e1 = sEA[row + 8];
        #pragma unroll
        for (int nt = 0; nt < 8; nt++) {
            int p = nt * 8 + tq * 2;
            size_t o0 = (size_t)(tok0 + row) * DINNER + h * PD + p;
            size_t o1 = (size_t)(tok0 + row + 8) * DINNER + h * PD + p;
            size_t x0 = (size_t)(tok0 + row) * CONVD + h * PD + p;
            size_t x1 = (size_t)(tok0 + row + 8) * CONVD + h * PD + p;
            y[o0]     += e0 * acc[mt][nt][0] + Dp * xBC[x0];
            y[o0 + 1] += e0 * acc[mt][nt][1] + Dp * xBC[x0 + 1];
            y[o1]     += e1 * acc[mt][nt][2] + Dp * xBC[x1];
            y[o1 + 1] += e1 * acc[mt][nt][3] + Dp * xBC[x1 + 1];
        }
    }
}

__global__ void __launch_bounds__(256)
gate_norm_kernel(const float* __restrict__ y, const float* __restrict__ zx,
                 const float* __restrict__ w, hf* __restrict__ yghi)
{
    int tok = blockIdx.x, tid = threadIdx.x;
    __shared__ float red[8];
    float g[8];
    float ss = 0.f;
    #pragma unroll
    for (int u = 0; u < 8; u++) {
        int d = tid + u * 256;
        float z  = zx[(size_t)tok * DIP + d];
        float yy = y[(size_t)tok * DINNER + d];
        float gv = yy * (z / (1.f + expf(-z)));
        g[u] = gv;
        ss += gv * gv;
    }
    float total = block_sum256(ss, red);
    float sc = rsqrtf(total * (1.f / DINNER) + 1e-5f);
    #pragma unroll
    for (int u = 0; u < 8; u++) {
        int d = tid + u * 256;
        yghi[(size_t)tok * DINNER + d] = __float2half_rn(g[u] * sc * w[d]);
    }
}

// ---------------- launch ----------------
extern "C" void kernel_launch(void* const* d_in, const int* in_sizes, int n_in,
                              void* d_out, int out_size)
{
    const float* x         = (const float*)d_in[0];
    const float* W_in      = (const float*)d_in[1];
    const float* W_z       = (const float*)d_in[2];
    const float* conv_w    = (const float*)d_in[3];
    const float* conv_b    = (const float*)d_in[4];
    const float* dt_bias   = (const float*)d_in[5];
    const float* A_log     = (const float*)d_in[6];
    const float* D_param   = (const float*)d_in[7];
    const float* norm_pre  = (const float*)d_in[8];
    const float* norm_gate = (const float*)d_in[9];
    const float* W_out     = (const float*)d_in[10];
    float* out = (float*)d_out;

    float* sc = nullptr;
    cudaGetSymbolAddress((void**)&sc, g_scratch);
    hf* XHI = (hf*)(sc + OFF_XHI);
    hf* WIH = (hf*)(sc + OFF_WIH);
    hf* WZH = (hf*)(sc + OFF_WZH);
    hf* WOH = (hf*)(sc + OFF_WOH);
    hf* HH  = (hf*)(sc + OFF_HH);
    hf* YGH = (hf*)(sc + OFF_YGH);
    hf* BCH = (hf*)(sc + OFF_BCH);
    float2* TAB = (float2*)(sc + OFF_TAB);

    cudaFuncSetAttribute(gemm_hf1, cudaFuncAttributeMaxDynamicSharedMemorySize, GEMM_SMEM);
    cudaFuncSetAttribute(ssd_part1, cudaFuncAttributeMaxDynamicSharedMemorySize, SSD1_SMEM);

    // 0) pre-computation (gemm #1 stays the 4th launch -> ncu profiles it)
    cvt_hi<<<(NTOK * DM / 4 + 255) / 256, 256>>>(x, XHI, NTOK * DM / 4);
    cvt_hi<<<(DM * DM / 4 + 255) / 256, 256>>>(W_in, WIH, DM * DM / 4);
    rope_tab_kernel<<<(TSEQ * 32 + 255) / 256, 256>>>(TAB);

    // 1) q = x @ W_in[:1024].T
    gemm_hf1<<<dim3(DM / BN, NTOK / BM, 1), 256, GEMM_SMEM>>>(
        XHI, WIH, sc + OFF_Q, nullptr, NTOK, DM, DM, DM, DM, DM, 0, 0, 0);

    cvt_hi<<<(DIP * DM / 4 + 255) / 256, 256>>>(W_z, WZH, DIP * DM / 4);
    cvt_hi<<<(DM * DINNER / 4 + 255) / 256, 256>>>(W_out, WOH, DM * DINNER / 4);

    // 2) rope + rmsnorm
    rope_norm_kernel<<<NTOK, 256>>>(sc + OFF_Q, HH, norm_pre, TAB);

    // 3) zxbcdt
    gemm_hf1<<<dim3((DIP + BN - 1) / BN, NTOK / BM, 1), 256, GEMM_SMEM>>>(
        HH, WZH, sc + OFF_ZX, nullptr, NTOK, DIP, DM, DM, DM, DIP, 0, 0, 0);

    // 4) dt
    dt_kernel<<<(NTOK * HS + 255) / 256, 256>>>(sc + OFF_ZX, dt_bias, sc + OFF_DT);

    // 5) conv + silu (4 tokens/thread)
    conv_kernel<<<((NTOK / 4) * (CONVD / 4) + 255) / 256, 256>>>(
        sc + OFF_ZX, conv_w, conv_b, sc + OFF_XBC, BCH);

    // 6) G = B . C^T batched
    gemm_hf1<<<dim3(CH / BN, CH / BM, 16), 256, GEMM_SMEM>>>(
        BCH, BCH + DS, sc + OFF_G, nullptr,
        CH, CH, DS, 256, 256, CH,
        (size_t)CH * 256, (size_t)CH * 256, (size_t)CH * CH);

    // 7) SSD part1
    ssd_part1<<<dim3(HS, NC, 2), 256, SSD1_SMEM>>>(
        sc + OFF_XBC, sc + OFF_DT, A_log, sc + OFF_G, BCH,
        sc + OFF_Y, sc + OFF_ST, sc + OFF_ASUM, sc + OFF_EACS);

    // 8) prefix
    ssd_prefix<<<dim3(HS, 2), 256>>>(sc + OFF_ST, sc + OFF_ASUM);

    // 9) part2 (mma)
    ssd_part2<<<dim3(HS, NC, 2), 256>>>(
        sc + OFF_XBC, sc + OFF_ST, sc + OFF_EACS, D_param, BCH, sc + OFF_Y);

    // 10) gated rmsnorm
    gate_norm_kernel<<<NTOK, 256>>>(sc + OFF_Y, sc + OFF_ZX, norm_gate, YGH);

    // 11) out-proj + residual
    gemm_hf1<<<dim3(DM / BN, NTOK / BM, 1), 256, GEMM_SMEM>>>(
        YGH, WOH, out, sc + OFF_Q, NTOK, DM, DINNER, DINNER, DINNER, DM, 0, 0, 0);
}